// round 8
// baseline (speedup 1.0000x reference)
#include <cuda_runtime.h>

#define N_PATIENT 50000
#define N_GENE    20000
#define N_EDGE    640000
#define P_DIM 64
#define G_DIM 32
#define H     128
#define OUT   8
#define TR    64      // rows per tile
#define TPAD  66      // padded row stride (floats) for transposed tiles
#define NT    256

typedef unsigned long long u64;

// Scratch (no cudaMalloc allowed)
__device__ float d_g  [N_GENE    * H];
__device__ float d_agg[N_PATIENT * H];
__device__ float d_p  [N_PATIENT * H];

// ---- packed f32x2 helpers ----
__device__ __forceinline__ void fma2(u64& c, u64 a, u64 b) {
    asm("fma.rn.f32x2 %0,%1,%2,%0;" : "+l"(c) : "l"(a), "l"(b));
}
__device__ __forceinline__ u64 dupf(float a) {
    u64 r; asm("mov.b64 %0,{%1,%1};" : "=l"(r) : "f"(a)); return r;
}
__device__ __forceinline__ float2 unpk(u64 v) {
    float2 r; asm("mov.b64 {%0,%1},%2;" : "=f"(r.x), "=f"(r.y) : "l"(v)); return r;
}

// ---------------------------------------------------------------- zero agg
__global__ void __launch_bounds__(NT) zero_kernel() {
    int i = blockIdx.x * blockDim.x + threadIdx.x;
    const int n4 = N_PATIENT * H / 4;
    if (i < n4) ((float4*)d_agg)[i] = make_float4(0.f, 0.f, 0.f, 0.f);
}

// ---------------------------------------------------------------- helpers
// load TR rows x K cols of X into transposed padded tile XT[k][r]
template<int K>
__device__ __forceinline__ void load_T(float* XT, const float* __restrict__ X,
                                       int row0, int nrows, int t) {
    for (int i = t; i < TR * K / 4; i += NT) {
        int r = i % TR, kq = i / TR;     // lanes get consecutive r -> conflict-free STS
        int gr = row0 + r;
        float4 v = make_float4(0.f, 0.f, 0.f, 0.f);
        if (gr < nrows) v = *(const float4*)&X[gr * K + kq * 4];
        XT[(4 * kq + 0) * TPAD + r] = v.x;
        XT[(4 * kq + 1) * TPAD + r] = v.y;
        XT[(4 * kq + 2) * TPAD + r] = v.z;
        XT[(4 * kq + 3) * TPAD + r] = v.w;
    }
}

// acc[r][j] covers rows {2*lane+r}, cols {c0+2j, c0+2j+1}; bias from GLOBAL
__device__ __forceinline__ void init_bias(u64 acc[2][8],
                                          const float* __restrict__ b, int c0) {
    const ulonglong2* bp = (const ulonglong2*)&b[c0];
    ulonglong2 b0 = bp[0], b1 = bp[1], b2 = bp[2], b3 = bp[3];
    u64 B[8] = {b0.x, b0.y, b1.x, b1.y, b2.x, b2.y, b3.x, b3.y};
    #pragma unroll
    for (int r = 0; r < 2; r++)
        #pragma unroll
        for (int j = 0; j < 8; j++) acc[r][j] = B[j];
}

// warp GEMM: acc += AT^T @ Wa (+ BT^T @ Wb). AT/BT: [K][TPAD] SMEM tiles,
// Wa/Wb: [K][H] row-major in GLOBAL (uniform-address LDG broadcast, L1/L2-hot).
template<int K, bool DUAL>
__device__ __forceinline__ void wgemm(
    u64 acc[2][8],
    const float* AT, const float* BT,
    const float* __restrict__ Wa, const float* __restrict__ Wb,
    int c0, int lane)
{
    #pragma unroll 4
    for (int k = 0; k < K; k++) {
        const ulonglong2* wa = (const ulonglong2*)&Wa[k * H + c0];
        ulonglong2 w0 = wa[0], w1 = wa[1], w2 = wa[2], w3 = wa[3];
        float2 a = *(const float2*)&AT[k * TPAD + 2 * lane];
        u64 a0 = dupf(a.x), a1 = dupf(a.y);
        fma2(acc[0][0], a0, w0.x); fma2(acc[0][1], a0, w0.y);
        fma2(acc[0][2], a0, w1.x); fma2(acc[0][3], a0, w1.y);
        fma2(acc[0][4], a0, w2.x); fma2(acc[0][5], a0, w2.y);
        fma2(acc[0][6], a0, w3.x); fma2(acc[0][7], a0, w3.y);
        fma2(acc[1][0], a1, w0.x); fma2(acc[1][1], a1, w0.y);
        fma2(acc[1][2], a1, w1.x); fma2(acc[1][3], a1, w1.y);
        fma2(acc[1][4], a1, w2.x); fma2(acc[1][5], a1, w2.y);
        fma2(acc[1][6], a1, w3.x); fma2(acc[1][7], a1, w3.y);
        if (DUAL) {
            const ulonglong2* wb = (const ulonglong2*)&Wb[k * H + c0];
            ulonglong2 v0 = wb[0], v1 = wb[1], v2 = wb[2], v3 = wb[3];
            float2 b = *(const float2*)&BT[k * TPAD + 2 * lane];
            u64 b0 = dupf(b.x), b1 = dupf(b.y);
            fma2(acc[0][0], b0, v0.x); fma2(acc[0][1], b0, v0.y);
            fma2(acc[0][2], b0, v1.x); fma2(acc[0][3], b0, v1.y);
            fma2(acc[0][4], b0, v2.x); fma2(acc[0][5], b0, v2.y);
            fma2(acc[0][6], b0, v3.x); fma2(acc[0][7], b0, v3.y);
            fma2(acc[1][0], b1, v0.x); fma2(acc[1][1], b1, v0.y);
            fma2(acc[1][2], b1, v1.x); fma2(acc[1][3], b1, v1.y);
            fma2(acc[1][4], b1, v2.x); fma2(acc[1][5], b1, v2.y);
            fma2(acc[1][6], b1, v3.x); fma2(acc[1][7], b1, v3.y);
        }
    }
}

// relu(acc) -> transposed tile OT[c][r]
__device__ __forceinline__ void store_relu_T(const u64 acc[2][8], float* OT,
                                             int c0, int lane) {
    #pragma unroll
    for (int j = 0; j < 8; j++) {
        float2 p0 = unpk(acc[0][j]);   // row 2*lane,   cols c0+2j, c0+2j+1
        float2 p1 = unpk(acc[1][j]);   // row 2*lane+1
        *(float2*)&OT[(c0 + 2 * j)     * TPAD + 2 * lane] =
            make_float2(fmaxf(p0.x, 0.f), fmaxf(p1.x, 0.f));
        *(float2*)&OT[(c0 + 2 * j + 1) * TPAD + 2 * lane] =
            make_float2(fmaxf(p0.y, 0.f), fmaxf(p1.y, 0.f));
    }
}

// ---------------------------------------------------------------- fused 2-layer MLP
template<int K>
__device__ __forceinline__ void mlp2_body(
    float* sm, const float* __restrict__ X,
    const float* __restrict__ W1, const float* __restrict__ b1,
    const float* __restrict__ W2, const float* __restrict__ b2,
    float* __restrict__ Y, int nrows)
{
    float* sXT = sm;                 // K*TPAD
    float* sHT = sXT + K * TPAD;     // H*TPAD

    const int t = threadIdx.x, lane = t & 31, wid = t >> 5, c0 = wid * 16;
    const int row0 = blockIdx.x * TR;
    load_T<K>(sXT, X, row0, nrows, t);
    __syncthreads();

    u64 acc[2][8];
    init_bias(acc, b1, c0);
    wgemm<K, false>(acc, sXT, nullptr, W1, nullptr, c0, lane);
    store_relu_T(acc, sHT, c0, lane);
    __syncthreads();

    init_bias(acc, b2, c0);
    wgemm<H, false>(acc, sHT, nullptr, W2, nullptr, c0, lane);

    #pragma unroll
    for (int r = 0; r < 2; r++) {
        int gr = row0 + 2 * lane + r;
        if (gr < nrows) {
            float2 p0 = unpk(acc[r][0]), p1 = unpk(acc[r][1]);
            float2 p2 = unpk(acc[r][2]), p3 = unpk(acc[r][3]);
            float2 p4 = unpk(acc[r][4]), p5 = unpk(acc[r][5]);
            float2 p6 = unpk(acc[r][6]), p7 = unpk(acc[r][7]);
            *(float4*)&Y[gr * H + c0]      = make_float4(p0.x, p0.y, p1.x, p1.y);
            *(float4*)&Y[gr * H + c0 + 4]  = make_float4(p2.x, p2.y, p3.x, p3.y);
            *(float4*)&Y[gr * H + c0 + 8]  = make_float4(p4.x, p4.y, p5.x, p5.y);
            *(float4*)&Y[gr * H + c0 + 12] = make_float4(p6.x, p6.y, p7.x, p7.y);
        }
    }
}

__global__ void __launch_bounds__(NT, 2) gene_kernel(
    const float* X, const float* W1, const float* b1,
    const float* W2, const float* b2)
{
    extern __shared__ float sm[];
    mlp2_body<G_DIM>(sm, X, W1, b1, W2, b2, d_g, N_GENE);
}

__global__ void __launch_bounds__(NT, 2) patient_kernel(
    const float* X, const float* W1, const float* b1,
    const float* W2, const float* b2)
{
    extern __shared__ float sm[];
    mlp2_body<P_DIM>(sm, X, W1, b1, W2, b2, d_p, N_PATIENT);
}

// ---------------------------------------------------------------- edge scatter
__global__ void __launch_bounds__(NT) scatter_kernel(const int* __restrict__ edges) {
    int gtid = blockIdx.x * blockDim.x + threadIdx.x;
    int e = gtid >> 5;
    if (e >= N_EDGE) return;
    int lane = threadIdx.x & 31;
    int src = edges[e];
    int dst = edges[N_EDGE + e];
    float4 v = *(const float4*)&d_g[src * H + lane * 4];
    float* p = &d_agg[dst * H + lane * 4];
    asm volatile("red.global.add.v4.f32 [%0], {%1,%2,%3,%4};"
                 :: "l"(p), "f"(v.x), "f"(v.y), "f"(v.z), "f"(v.w)
                 : "memory");
}

// ---------------------------------------------------------------- fused SAGE1+SAGE2+FC
__global__ void __launch_bounds__(NT, 2) sage_fused_kernel(
    const float* W1l, const float* b1l, const float* W1r,
    const float* W2l, const float* b2l, const float* W2r,
    const float* Wfc, const float* bfc, float* out)
{
    extern __shared__ float sm[];
    float* sWfc = sm;                   // H*OUT
    float* sbfc = sWfc + H * OUT;       // OUT (pad to 16)
    float* sAgT = sbfc + 16;            // H*TPAD
    float* sXT  = sAgT + H * TPAD;      // H*TPAD (p, then t)

    const int t = threadIdx.x, lane = t & 31, wid = t >> 5, c0 = wid * 16;
    const int row0 = blockIdx.x * TR;

    for (int i = t; i < H * OUT / 4; i += NT)
        ((float4*)sWfc)[i] = ((const float4*)Wfc)[i];
    if (t < OUT) sbfc[t] = bfc[t];
    load_T<H>(sAgT, d_agg, row0, N_PATIENT, t);
    load_T<H>(sXT,  d_p,   row0, N_PATIENT, t);
    __syncthreads();

    // layer 1: t = relu(agg@W1l + b1l + p@W1r)
    u64 acc[2][8];
    init_bias(acc, b1l, c0);
    wgemm<H, true>(acc, sAgT, sXT, W1l, W1r, c0, lane);
    __syncthreads();                       // all reads of sXT done
    store_relu_T(acc, sXT, c0, lane);      // t overwrites p tile
    __syncthreads();

    // layer 2: p2 = relu(agg@W2l + b2l + t@W2r)
    init_bias(acc, b2l, c0);
    wgemm<H, true>(acc, sAgT, sXT, W2l, W2r, c0, lane);
    __syncthreads();                       // all reads of sAgT done
    store_relu_T(acc, sAgT, c0, lane);     // p2 overwrites agg tile
    __syncthreads();

    // FC: out[r][o] = bfc[o] + sum_c p2[r][c] * Wfc[c][o]
    int r = t & 63, og = t >> 6;           // og in 0..3 -> 2 output cols each
    float s0 = sbfc[2 * og], s1 = sbfc[2 * og + 1];
    #pragma unroll 4
    for (int c = 0; c < H; c++) {
        float pv = sAgT[c * TPAD + r];
        s0 += pv * sWfc[c * OUT + 2 * og];
        s1 += pv * sWfc[c * OUT + 2 * og + 1];
    }
    int gr = row0 + r;
    if (gr < N_PATIENT) {
        out[gr * OUT + 2 * og]     = s0;
        out[gr * OUT + 2 * og + 1] = s1;
    }
}

// ---------------------------------------------------------------- launch
extern "C" void kernel_launch(void* const* d_in, const int* in_sizes, int n_in,
                              void* d_out, int out_size)
{
    const float* x_p  = (const float*)d_in[0];
    const float* x_g  = (const float*)d_in[1];
    const int*   eidx = (const int*)  d_in[2];
    const float* W_p1 = (const float*)d_in[3];
    const float* b_p1 = (const float*)d_in[4];
    const float* W_p2 = (const float*)d_in[5];
    const float* b_p2 = (const float*)d_in[6];
    const float* W_g1 = (const float*)d_in[7];
    const float* b_g1 = (const float*)d_in[8];
    const float* W_g2 = (const float*)d_in[9];
    const float* b_g2 = (const float*)d_in[10];
    const float* W1_l = (const float*)d_in[11];
    const float* b1_l = (const float*)d_in[12];
    const float* W1_r = (const float*)d_in[13];
    const float* W2_l = (const float*)d_in[14];
    const float* b2_l = (const float*)d_in[15];
    const float* W2_r = (const float*)d_in[16];
    const float* W_fc = (const float*)d_in[17];
    const float* b_fc = (const float*)d_in[18];
    float* out = (float*)d_out;

    const int smem_gene    = (G_DIM * TPAD + H * TPAD) * 4;
    const int smem_patient = (P_DIM * TPAD + H * TPAD) * 4;
    const int smem_sage    = (H * OUT + 16 + 2 * H * TPAD) * 4;

    cudaFuncSetAttribute(gene_kernel,       cudaFuncAttributeMaxDynamicSharedMemorySize, smem_gene);
    cudaFuncSetAttribute(patient_kernel,    cudaFuncAttributeMaxDynamicSharedMemorySize, smem_patient);
    cudaFuncSetAttribute(sage_fused_kernel, cudaFuncAttributeMaxDynamicSharedMemorySize, smem_sage);

    const int zero_blocks    = (N_PATIENT * H / 4 + NT - 1) / NT;
    const int gene_blocks    = (N_GENE    + TR - 1) / TR;
    const int patient_blocks = (N_PATIENT + TR - 1) / TR;
    const int scatter_blocks = (N_EDGE * 32 + NT - 1) / NT;

    zero_kernel      <<<zero_blocks, NT>>>();
    gene_kernel      <<<gene_blocks, NT, smem_gene>>>(x_g, W_g1, b_g1, W_g2, b_g2);
    patient_kernel   <<<patient_blocks, NT, smem_patient>>>(x_p, W_p1, b_p1, W_p2, b_p2);
    scatter_kernel   <<<scatter_blocks, NT>>>(eidx);
    sage_fused_kernel<<<patient_blocks, NT, smem_sage>>>(
        W1_l, b1_l, W1_r, W2_l, b2_l, W2_r, W_fc, b_fc, out);
}

// round 9
// speedup vs baseline: 1.0722x; 1.0722x over previous
#include <cuda_runtime.h>

#define N_PATIENT 50000
#define N_GENE    20000
#define N_EDGE    640000
#define P_DIM 64
#define G_DIM 32
#define H     128
#define OUT   8
#define TR    64      // rows per tile
#define TPAD  66      // padded row stride (floats) for transposed tiles
#define NT    256
#define GRID_P 296    // persistent grid: 2 CTAs x 148 SMs

typedef unsigned long long u64;

// Scratch (no cudaMalloc allowed)
__device__ float d_g  [N_GENE    * H];
__device__ float d_agg[N_PATIENT * H];
__device__ float d_p  [N_PATIENT * H];
__device__ float d_t  [N_PATIENT * H];

// ---- packed f32x2 helpers ----
__device__ __forceinline__ void fma2(u64& c, u64 a, u64 b) {
    asm("fma.rn.f32x2 %0,%1,%2,%0;" : "+l"(c) : "l"(a), "l"(b));
}
__device__ __forceinline__ u64 dupf(float a) {
    u64 r; asm("mov.b64 %0,{%1,%1};" : "=l"(r) : "f"(a)); return r;
}
__device__ __forceinline__ float2 unpk(u64 v) {
    float2 r; asm("mov.b64 {%0,%1},%2;" : "=f"(r.x), "=f"(r.y) : "l"(v)); return r;
}

// ---------------------------------------------------------------- zero agg
__global__ void __launch_bounds__(NT) zero_kernel() {
    int i = blockIdx.x * blockDim.x + threadIdx.x;
    const int n4 = N_PATIENT * H / 4;
    if (i < n4) ((float4*)d_agg)[i] = make_float4(0.f, 0.f, 0.f, 0.f);
}

// ---------------------------------------------------------------- helpers
// load TR rows x K cols of X into transposed padded tile XT[k][r]
template<int K>
__device__ __forceinline__ void load_T(float* XT, const float* __restrict__ X,
                                       int row0, int nrows, int t) {
    for (int i = t; i < TR * K / 4; i += NT) {
        int r = i % TR, kq = i / TR;     // lanes get consecutive r -> conflict-free STS
        int gr = row0 + r;
        float4 v = make_float4(0.f, 0.f, 0.f, 0.f);
        if (gr < nrows) v = *(const float4*)&X[gr * K + kq * 4];
        XT[(4 * kq + 0) * TPAD + r] = v.x;
        XT[(4 * kq + 1) * TPAD + r] = v.y;
        XT[(4 * kq + 2) * TPAD + r] = v.z;
        XT[(4 * kq + 3) * TPAD + r] = v.w;
    }
}

// ---------------------------------------------------------------- generic GEMM pass
// Y = [relu]( A @ W [+ bias] [+ prev] )   ; optional fused FC epilogue (K must be H)
// Persistent CTAs: weights loaded into SMEM ONCE per CTA, loop over row tiles.
template<int K, bool BIAS, bool PREV, bool RELU, bool FC>
__global__ void __launch_bounds__(NT, 2) pass_kernel(
    const float* __restrict__ A, const float* __restrict__ W,
    const float* __restrict__ bias, const float* prev, float* Y, int nrows,
    const float* __restrict__ Wfc, const float* __restrict__ bfc)
{
    extern __shared__ float sm[];
    float* sW  = sm;                 // K*H
    float* sAT = sW + K * H;         // K*TPAD

    const int t = threadIdx.x, lane = t & 31, wid = t >> 5, c0 = wid * 16;

    for (int i = t; i < K * H / 4; i += NT)
        ((float4*)sW)[i] = ((const float4*)W)[i];

    u64 B[8];
    if (BIAS) {
        const ulonglong2* bp = (const ulonglong2*)&bias[c0];
        ulonglong2 b0 = bp[0], b1 = bp[1], b2 = bp[2], b3 = bp[3];
        B[0] = b0.x; B[1] = b0.y; B[2] = b1.x; B[3] = b1.y;
        B[4] = b2.x; B[5] = b2.y; B[6] = b3.x; B[7] = b3.y;
    } else {
        #pragma unroll
        for (int j = 0; j < 8; j++) B[j] = 0ull;
    }

    const int ntiles = (nrows + TR - 1) / TR;
    for (int tile = blockIdx.x; tile < ntiles; tile += gridDim.x) {
        const int row0 = tile * TR;
        __syncthreads();                     // sAT free from previous iteration
        load_T<K>(sAT, A, row0, nrows, t);
        __syncthreads();

        u64 acc[2][8];
        #pragma unroll
        for (int r = 0; r < 2; r++)
            #pragma unroll
            for (int j = 0; j < 8; j++) acc[r][j] = B[j];

        #pragma unroll 4
        for (int k = 0; k < K; k++) {
            const ulonglong2* wa = (const ulonglong2*)&sW[k * H + c0];
            ulonglong2 w0 = wa[0], w1 = wa[1], w2 = wa[2], w3 = wa[3];
            float2 a = *(const float2*)&sAT[k * TPAD + 2 * lane];
            u64 a0 = dupf(a.x), a1 = dupf(a.y);
            fma2(acc[0][0], a0, w0.x); fma2(acc[0][1], a0, w0.y);
            fma2(acc[0][2], a0, w1.x); fma2(acc[0][3], a0, w1.y);
            fma2(acc[0][4], a0, w2.x); fma2(acc[0][5], a0, w2.y);
            fma2(acc[0][6], a0, w3.x); fma2(acc[0][7], a0, w3.y);
            fma2(acc[1][0], a1, w0.x); fma2(acc[1][1], a1, w0.y);
            fma2(acc[1][2], a1, w1.x); fma2(acc[1][3], a1, w1.y);
            fma2(acc[1][4], a1, w2.x); fma2(acc[1][5], a1, w2.y);
            fma2(acc[1][6], a1, w3.x); fma2(acc[1][7], a1, w3.y);
        }

        float v[2][16];
        #pragma unroll
        for (int r = 0; r < 2; r++)
            #pragma unroll
            for (int j = 0; j < 8; j++) {
                float2 p = unpk(acc[r][j]);
                v[r][2 * j] = p.x; v[r][2 * j + 1] = p.y;
            }

        #pragma unroll
        for (int r = 0; r < 2; r++) {
            int gr = row0 + 2 * lane + r;
            if (gr < nrows) {
                if (PREV) {
                    const float4* pp = (const float4*)&prev[gr * H + c0];
                    float4 q0 = pp[0], q1 = pp[1], q2 = pp[2], q3 = pp[3];
                    v[r][0] += q0.x;  v[r][1] += q0.y;  v[r][2] += q0.z;  v[r][3] += q0.w;
                    v[r][4] += q1.x;  v[r][5] += q1.y;  v[r][6] += q1.z;  v[r][7] += q1.w;
                    v[r][8] += q2.x;  v[r][9] += q2.y;  v[r][10] += q2.z; v[r][11] += q2.w;
                    v[r][12] += q3.x; v[r][13] += q3.y; v[r][14] += q3.z; v[r][15] += q3.w;
                }
                if (RELU) {
                    #pragma unroll
                    for (int j = 0; j < 16; j++) v[r][j] = fmaxf(v[r][j], 0.f);
                }
                if (!FC) {
                    float4* yp = (float4*)&Y[gr * H + c0];
                    yp[0] = make_float4(v[r][0],  v[r][1],  v[r][2],  v[r][3]);
                    yp[1] = make_float4(v[r][4],  v[r][5],  v[r][6],  v[r][7]);
                    yp[2] = make_float4(v[r][8],  v[r][9],  v[r][10], v[r][11]);
                    yp[3] = make_float4(v[r][12], v[r][13], v[r][14], v[r][15]);
                }
            }
        }

        if (FC) {
            __syncthreads();                 // all reads of sAT done
            #pragma unroll
            for (int j = 0; j < 16; j++) {   // transposed store of p2 tile
                sAT[(c0 + j) * TPAD + 2 * lane]     = v[0][j];
                sAT[(c0 + j) * TPAD + 2 * lane + 1] = v[1][j];
            }
            __syncthreads();
            int r = t & 63, og = t >> 6;     // 4 groups x 2 output cols
            float s0 = bfc[2 * og], s1 = bfc[2 * og + 1];
            #pragma unroll 4
            for (int c = 0; c < H; c++) {
                float pv = sAT[c * TPAD + r];
                s0 += pv * __ldg(&Wfc[c * OUT + 2 * og]);
                s1 += pv * __ldg(&Wfc[c * OUT + 2 * og + 1]);
            }
            int gr = row0 + r;
            if (gr < nrows) {
                Y[gr * OUT + 2 * og]     = s0;
                Y[gr * OUT + 2 * og + 1] = s1;
            }
        }
    }
}

// ---------------------------------------------------------------- edge scatter
__global__ void __launch_bounds__(NT) scatter_kernel(const int* __restrict__ edges) {
    int gtid = blockIdx.x * blockDim.x + threadIdx.x;
    int e = gtid >> 5;
    if (e >= N_EDGE) return;
    int lane = threadIdx.x & 31;
    int src = edges[e];
    int dst = edges[N_EDGE + e];
    float4 v = *(const float4*)&d_g[src * H + lane * 4];
    float* p = &d_agg[dst * H + lane * 4];
    asm volatile("red.global.add.v4.f32 [%0], {%1,%2,%3,%4};"
                 :: "l"(p), "f"(v.x), "f"(v.y), "f"(v.z), "f"(v.w)
                 : "memory");
}

// ---------------------------------------------------------------- launch
static inline int smem_for(int K) { return (K * H + K * TPAD) * 4; }

extern "C" void kernel_launch(void* const* d_in, const int* in_sizes, int n_in,
                              void* d_out, int out_size)
{
    const float* x_p  = (const float*)d_in[0];
    const float* x_g  = (const float*)d_in[1];
    const int*   eidx = (const int*)  d_in[2];
    const float* W_p1 = (const float*)d_in[3];
    const float* b_p1 = (const float*)d_in[4];
    const float* W_p2 = (const float*)d_in[5];
    const float* b_p2 = (const float*)d_in[6];
    const float* W_g1 = (const float*)d_in[7];
    const float* b_g1 = (const float*)d_in[8];
    const float* W_g2 = (const float*)d_in[9];
    const float* b_g2 = (const float*)d_in[10];
    const float* W1_l = (const float*)d_in[11];
    const float* b1_l = (const float*)d_in[12];
    const float* W1_r = (const float*)d_in[13];
    const float* W2_l = (const float*)d_in[14];
    const float* b2_l = (const float*)d_in[15];
    const float* W2_r = (const float*)d_in[16];
    const float* W_fc = (const float*)d_in[17];
    const float* b_fc = (const float*)d_in[18];
    float* out = (float*)d_out;

    float* g_t   = nullptr; cudaGetSymbolAddress((void**)&g_t,   d_t);
    float* g_p   = nullptr; cudaGetSymbolAddress((void**)&g_p,   d_p);
    float* g_g   = nullptr; cudaGetSymbolAddress((void**)&g_g,   d_g);
    float* g_agg = nullptr; cudaGetSymbolAddress((void**)&g_agg, d_agg);

    const int sm32 = smem_for(G_DIM), sm64 = smem_for(P_DIM), sm128 = smem_for(H);

    // template instantiations: <K, BIAS, PREV, RELU, FC>
    auto kG1  = pass_kernel<G_DIM, true,  false, true,  false>;
    auto kG2  = pass_kernel<H,     true,  false, false, false>;
    auto kP1  = pass_kernel<P_DIM, true,  false, true,  false>;
    auto kP2  = pass_kernel<H,     true,  false, false, false>;  // same sig as kG2
    auto kS1A = pass_kernel<H,     true,  false, false, false>;
    auto kS1B = pass_kernel<H,     false, true,  true,  false>;
    auto kS2B = pass_kernel<H,     false, true,  true,  true>;

    cudaFuncSetAttribute(kG1,  cudaFuncAttributeMaxDynamicSharedMemorySize, sm32);
    cudaFuncSetAttribute(kP1,  cudaFuncAttributeMaxDynamicSharedMemorySize, sm64);
    cudaFuncSetAttribute(kG2,  cudaFuncAttributeMaxDynamicSharedMemorySize, sm128);
    cudaFuncSetAttribute(kS1B, cudaFuncAttributeMaxDynamicSharedMemorySize, sm128);
    cudaFuncSetAttribute(kS2B, cudaFuncAttributeMaxDynamicSharedMemorySize, sm128);

    const int zero_blocks    = (N_PATIENT * H / 4 + NT - 1) / NT;
    const int scatter_blocks = (N_EDGE * 32 + NT - 1) / NT;

    zero_kernel<<<zero_blocks, NT>>>();

    // gene MLP: tmp = relu(x_g@Wg1+b) -> d_t ; d_g = tmp@Wg2 + b
    kG1<<<GRID_P, NT, sm32>>>(x_g, W_g1, b_g1, nullptr, g_t, N_GENE, nullptr, nullptr);
    kG2<<<GRID_P, NT, sm128>>>(g_t, W_g2, b_g2, nullptr, g_g, N_GENE, nullptr, nullptr);

    // patient MLP: tmp = relu(x_p@Wp1+b) -> d_t ; d_p = tmp@Wp2 + b
    kP1<<<GRID_P, NT, sm64>>>(x_p, W_p1, b_p1, nullptr, g_t, N_PATIENT, nullptr, nullptr);
    kP2<<<GRID_P, NT, sm128>>>(g_t, W_p2, b_p2, nullptr, g_p, N_PATIENT, nullptr, nullptr);

    // scatter: d_agg += d_g[src] per edge
    scatter_kernel<<<scatter_blocks, NT>>>(eidx);

    // SAGE1: d_t = agg@W1l + b1l ; d_t = relu(d_t + d_p@W1r)  (in-place)
    kS1A<<<GRID_P, NT, sm128>>>(g_agg, W1_l, b1_l, nullptr, g_t, N_PATIENT, nullptr, nullptr);
    kS1B<<<GRID_P, NT, sm128>>>(g_p, W1_r, nullptr, g_t, g_t, N_PATIENT, nullptr, nullptr);

    // SAGE2: d_p = agg@W2l + b2l ; out = FC(relu(d_p + d_t@W2r))
    kS1A<<<GRID_P, NT, sm128>>>(g_agg, W2_l, b2_l, nullptr, g_p, N_PATIENT, nullptr, nullptr);
    kS2B<<<GRID_P, NT, sm128>>>(g_t, W2_r, nullptr, g_p, out, N_PATIENT, W_fc, b_fc);
}

// round 11
// speedup vs baseline: 1.7831x; 1.6631x over previous
#include <cuda_runtime.h>
#include <cuda_bf16.h>
#include <cstdint>

#define N_PATIENT 50000
#define N_GENE    20000
#define N_EDGE    640000
#define P_DIM 64
#define G_DIM 32
#define H     128
#define OUT   8
#define NT    256
#define MTILE 128
#define GRID_MMA 148

// tcgen05 is only encodable in the arch-specific (sm_103a) compile pass.
// The compute_103 PTX fallback pass gets stubs (never executed on this GPU).
#if defined(__CUDA_ARCH__) && (defined(__CUDA_ARCH_FEAT_SM103_ALL) || \
    defined(__CUDA_ARCH_FEAT_SM100_ALL) || defined(__CUDA_ARCH_FEAT_SM101_ALL))
#define HAS_TC5 1
#else
#define HAS_TC5 0
#endif

// ---------------- device scratch (no cudaMalloc allowed) ----------------
__device__ float d_g  [N_GENE    * H];
__device__ float d_agg[N_PATIENT * H];
__device__ float d_p  [N_PATIENT * H];
__device__ float d_t  [N_PATIENT * H];
__device__ __nv_bfloat16 d_wsp[8][H * 384];   // split weights [H][KP]

// ---------------- ptx helpers ----------------
__device__ __forceinline__ uint32_t cvta_s(const void* p) {
    uint32_t a;
    asm("{.reg .u64 t; cvta.to.shared.u64 t, %1; cvt.u32.u64 %0, t;}" : "=r"(a) : "l"(p));
    return a;
}
__device__ __forceinline__ bool elect1() {
    uint32_t p;
    asm volatile("{.reg .pred p; elect.sync _|p, 0xFFFFFFFF; selp.b32 %0,1,0,p;}" : "=r"(p));
    return p != 0;
}
__device__ __forceinline__ void sts128(uint32_t addr, uint32_t a, uint32_t b,
                                       uint32_t c, uint32_t d) {
    asm volatile("st.shared.v4.b32 [%0], {%1,%2,%3,%4};"
                 :: "r"(addr), "r"(a), "r"(b), "r"(c), "r"(d) : "memory");
}
__device__ __forceinline__ void mbar_init(uint32_t addr, uint32_t cnt) {
    asm volatile("mbarrier.init.shared.b64 [%0], %1;" :: "r"(addr), "r"(cnt) : "memory");
}
__device__ __forceinline__ void mbar_inval(uint32_t addr) {
    asm volatile("mbarrier.inval.shared.b64 [%0];" :: "r"(addr) : "memory");
}
__device__ __forceinline__ void mbar_wait(uint32_t mbar, uint32_t parity) {
    uint32_t done;
    asm volatile(
        "{\n\t.reg .pred p;\n\t"
        "mbarrier.try_wait.parity.acquire.cta.shared::cta.b64 p, [%1], %2;\n\t"
        "selp.b32 %0, 1, 0, p;\n\t}"
        : "=r"(done) : "r"(mbar), "r"(parity) : "memory");
    if (!done) {
        asm volatile(
            "{\n\t.reg .pred P1;\n\t"
            "WAIT_LOOP_%=:\n\t"
            "mbarrier.try_wait.parity.acquire.cta.shared::cta.b64 P1, [%0], %1, 0x989680;\n\t"
            "@P1 bra.uni WAIT_DONE_%=;\n\t"
            "bra.uni WAIT_LOOP_%=;\n\t"
            "WAIT_DONE_%=:\n\t}"
            :: "r"(mbar), "r"(parity) : "memory");
    }
}
__device__ __forceinline__ void tmem_alloc(uint32_t dst_smem, uint32_t ncols) {
#if HAS_TC5
    asm volatile("tcgen05.alloc.cta_group::1.sync.aligned.shared::cta.b32 [%0], %1;"
                 :: "r"(dst_smem), "r"(ncols) : "memory");
#endif
}
__device__ __forceinline__ void tmem_dealloc(uint32_t tmem, uint32_t ncols) {
#if HAS_TC5
    asm volatile("tcgen05.dealloc.cta_group::1.sync.aligned.b32 %0, %1;" :: "r"(tmem), "r"(ncols));
#endif
}
__device__ __forceinline__ void mma_f16_ss(uint32_t d_tmem, uint64_t a_desc,
                                           uint64_t b_desc, uint32_t idesc, bool en) {
#if HAS_TC5
    uint32_t e = en ? 1u : 0u;
    asm volatile(
        "{\n\t.reg .pred p;\n\t"
        "setp.ne.u32 p, %5, 0;\n\t"
        "tcgen05.mma.cta_group::1.kind::f16 [%0], %1, %2, %3, {%4,%4,%4,%4}, p;\n\t}"
        :: "r"(d_tmem), "l"(a_desc), "l"(b_desc), "r"(idesc), "r"(0u), "r"(e)
        : "memory");
#endif
}
__device__ __forceinline__ void mma_commit(uint32_t mbar) {
#if HAS_TC5
    asm volatile("tcgen05.commit.cta_group::1.mbarrier::arrive::one.shared::cluster.b64 [%0];"
                 :: "r"(mbar) : "memory");
#else
    // keep barrier semantics valid in stub pass
    asm volatile("mbarrier.arrive.shared.b64 _, [%0];" :: "r"(mbar) : "memory");
#endif
}
__device__ __forceinline__ void fence_async_proxy() {
    asm volatile("fence.proxy.async.shared::cta;" ::: "memory");
}
__device__ __forceinline__ void tc_fence_after() {
#if HAS_TC5
    asm volatile("tcgen05.fence::after_thread_sync;" ::: "memory");
#endif
}
__device__ __forceinline__ void tc_fence_before() {
#if HAS_TC5
    asm volatile("tcgen05.fence::before_thread_sync;" ::: "memory");
#endif
}
__device__ __forceinline__ void tc_wait_ld() {
#if HAS_TC5
    asm volatile("tcgen05.wait::ld.sync.aligned;" ::: "memory");
#endif
}
__device__ __forceinline__ void ldtm32(uint32_t* r, uint32_t tmem_addr) {
#if HAS_TC5
    asm volatile(
        "tcgen05.ld.sync.aligned.32x32b.x32.b32 "
        "{%0, %1, %2, %3, %4, %5, %6, %7, "
        " %8, %9, %10, %11, %12, %13, %14, %15, "
        " %16, %17, %18, %19, %20, %21, %22, %23, "
        " %24, %25, %26, %27, %28, %29, %30, %31}, [%32];"
        : "=r"(r[0]),  "=r"(r[1]),  "=r"(r[2]),  "=r"(r[3]),
          "=r"(r[4]),  "=r"(r[5]),  "=r"(r[6]),  "=r"(r[7]),
          "=r"(r[8]),  "=r"(r[9]),  "=r"(r[10]), "=r"(r[11]),
          "=r"(r[12]), "=r"(r[13]), "=r"(r[14]), "=r"(r[15]),
          "=r"(r[16]), "=r"(r[17]), "=r"(r[18]), "=r"(r[19]),
          "=r"(r[20]), "=r"(r[21]), "=r"(r[22]), "=r"(r[23]),
          "=r"(r[24]), "=r"(r[25]), "=r"(r[26]), "=r"(r[27]),
          "=r"(r[28]), "=r"(r[29]), "=r"(r[30]), "=r"(r[31])
        : "r"(tmem_addr));
#else
    for (int i = 0; i < 32; i++) r[i] = 0u;
#endif
}

static constexpr uint64_t DESC_BASE =
    (2ull << 61) | (1ull << 46) | (64ull << 32) | (1ull << 16);  // SW128, Blackwell, SBO=64, LBO=1
__device__ __forceinline__ uint64_t make_desc(uint32_t addr) {
    return DESC_BASE | ((uint64_t)(addr >> 4) & 0x3FFF);
}
__device__ __forceinline__ uint32_t swz(uint32_t off) { return off ^ ((off >> 3) & 0x70); }

// ---------------- zero agg ----------------
__global__ void __launch_bounds__(NT) zero_kernel() {
    int i = blockIdx.x * blockDim.x + threadIdx.x;
    const int n4 = N_PATIENT * H / 4;
    if (i < n4) ((float4*)d_agg)[i] = make_float4(0.f, 0.f, 0.f, 0.f);
}

// ---------------- weight split prep: W[K][H] f32 -> W'[H][KP] bf16 ([W0,W1,W0,pad]) ----
struct PrepArgs { const float* src[8]; int K[8]; int KP[8]; };
__global__ void __launch_bounds__(NT) prep_kernel(PrepArgs a) {
    int m = blockIdx.y;
    int K = a.K[m], KP = a.KP[m];
    const float* W = a.src[m];
    __nv_bfloat16* D = d_wsp[m];
    int tot = H * KP;
    int i = blockIdx.x * blockDim.x + threadIdx.x;
    if (i >= tot) return;
    int c = i / KP, s = i % KP;
    __nv_bfloat16 v;
    if (s < K) {
        v = __float2bfloat16(W[s * H + c]);
    } else if (s < 2 * K) {
        float w = W[(s - K) * H + c];
        float w0 = __bfloat162float(__float2bfloat16(w));
        v = __float2bfloat16(w - w0);
    } else if (s < 3 * K) {
        v = __float2bfloat16(W[(s - 2 * K) * H + c]);
    } else {
        v = __float2bfloat16(0.f);
    }
    D[c * KP + s] = v;
}

// ---------------- staging helpers ----------------
// A tile: M=128 rows x KP bf16 slots, blocked SW128 atoms (16 atom-rows)
__device__ __forceinline__ uint32_t offA(int row, int s) {
    return ((row >> 3) + (s >> 6) * 16) * 1024 + (row & 7) * 128 + (s & 63) * 2;
}
template<int K, int KP>
__device__ __forceinline__ void stageA(uint32_t sA, const float* __restrict__ A,
                                       int row0, int nrows, int t) {
    const int GP = K / 8;
    for (int g = t; g < MTILE * GP; g += NT) {
        int row = g / GP, k8 = g % GP;
        int gr = row0 + row;
        float4 v0 = make_float4(0.f,0.f,0.f,0.f), v1 = v0;
        if (gr < nrows) {
            const float4* src = (const float4*)&A[gr * K + k8 * 8];
            v0 = src[0]; v1 = src[1];
        }
        float f[8] = {v0.x, v0.y, v0.z, v0.w, v1.x, v1.y, v1.z, v1.w};
        uint32_t p0[4], p1[4];
        #pragma unroll
        for (int j = 0; j < 4; j++) {
            __nv_bfloat16 b0 = __float2bfloat16(f[2*j]);
            __nv_bfloat16 b1 = __float2bfloat16(f[2*j+1]);
            __nv_bfloat162 q0 = __halves2bfloat162(b0, b1);
            p0[j] = *(uint32_t*)&q0;
            __nv_bfloat16 c0 = __float2bfloat16(f[2*j]   - __bfloat162float(b0));
            __nv_bfloat16 c1 = __float2bfloat16(f[2*j+1] - __bfloat162float(b1));
            __nv_bfloat162 q1 = __halves2bfloat162(c0, c1);
            p1[j] = *(uint32_t*)&q1;
        }
        int s = k8 * 8;
        sts128(sA + swz(offA(row, s)),         p0[0], p0[1], p0[2], p0[3]);
        sts128(sA + swz(offA(row, K + s)),     p0[0], p0[1], p0[2], p0[3]);
        sts128(sA + swz(offA(row, 2*K + s)),   p1[0], p1[1], p1[2], p1[3]);
    }
    if (KP > 3 * K) {
        const int PG = (KP - 3 * K) / 8;
        for (int g = t; g < MTILE * PG; g += NT) {
            int row = g / PG, k8 = g % PG;
            sts128(sA + swz(offA(row, 3*K + k8*8)), 0u, 0u, 0u, 0u);
        }
    }
}
// B tile: NCTA rows x KP bf16, blocked SW128 atoms (NCTA/8 atom-rows)
template<int KP, int NCTA>
__device__ __forceinline__ void stageB(uint32_t sB, const __nv_bfloat16* __restrict__ Wp,
                                       int half, int t) {
    const int GP = KP / 8;
    const uint4* src = (const uint4*)(Wp + half * NCTA * KP);
    for (int g = t; g < NCTA * GP; g += NT) {
        int r = g / GP, s8 = g % GP;
        uint4 v = src[g];
        int s = s8 * 8;
        uint32_t off = ((r >> 3) + (s >> 6) * (NCTA / 8)) * 1024 + (r & 7) * 128 + (s & 63) * 2;
        sts128(sB + swz(off), v.x, v.y, v.z, v.w);
    }
}

// ---------------- tensor-core GEMM pass ----------------
// Y[:,all H cols] = [relu]( A1@W1 (+ A2@W2) + bias ),  W' pre-split bf16 [H][KP]
template<int K, int KP, int NCTA, bool DUAL, bool RELU>
__global__ void __launch_bounds__(NT) __cluster_dims__(1, 1, 1)
mma_pass(const float* __restrict__ A1, const float* __restrict__ A2,
         const __nv_bfloat16* __restrict__ W1p, const __nv_bfloat16* __restrict__ W2p,
         const float* __restrict__ bias, float* __restrict__ Y, int nrows)
{
    extern __shared__ char smx[];
    __shared__ uint32_t s_tmemptr;
    __shared__ __align__(8) unsigned long long s_mbar;
    __shared__ float sb[H];

    const int t = threadIdx.x, lane = t & 31, wid = t >> 5;
    const uint32_t mbar = cvta_s(&s_mbar);

    uint32_t base = cvta_s(smx);
    uint32_t sA  = (base + 1023u) & ~1023u;
    const uint32_t A_BYTES = MTILE * KP * 2;
    const uint32_t B_BYTES = NCTA * KP * 2;
    uint32_t sB1 = sA + A_BYTES;
    uint32_t sB2 = sB1 + B_BYTES;

    if (wid == 0) tmem_alloc(cvta_s(&s_tmemptr), 128);
    if (t == 0) mbar_init(mbar, 1);
    if (t < H) sb[t] = bias[t];
    __syncthreads();
    const uint32_t tmem = s_tmemptr;

    const uint32_t idesc = (1u << 4) | (1u << 7) | (1u << 10) |
                           ((NCTA / 8) << 17) | (8u << 24);
    const int NCH = KP / 16;
    const int BSTRIDE = (NCTA / 8) * 64;    // desc units per atom-col for B
    const int ntiles = (nrows + MTILE - 1) / MTILE;
    uint32_t ph = 0;

    #pragma unroll 1
    for (int half = 0; half < H / NCTA; half++) {
        if (half) __syncthreads();
        stageB<KP, NCTA>(sB1, W1p, half, t);
        if (DUAL) stageB<KP, NCTA>(sB2, W2p, half, t);
        __syncthreads();
        const uint64_t descA  = make_desc(sA);
        const uint64_t descB1 = make_desc(sB1);
        const uint64_t descB2 = make_desc(sB2);

        #pragma unroll 1
        for (int tile = blockIdx.x; tile < ntiles; tile += gridDim.x) {
            const int row0 = tile * MTILE;

            stageA<K, KP>(sA, A1, row0, nrows, t);
            __syncthreads();
            if (wid == 0) {
                if (elect1()) {
                    fence_async_proxy();
                    #pragma unroll 1
                    for (int c = 0; c < NCH; c++) {
                        uint64_t ad = descA  + (uint32_t)((c >> 2) * 1024 + (c & 3) * 2);
                        uint64_t bd = descB1 + (uint32_t)((c >> 2) * BSTRIDE + (c & 3) * 2);
                        mma_f16_ss(tmem, ad, bd, idesc, c > 0);
                    }
                    mma_commit(mbar);
                }
            }
            mbar_wait(mbar, ph); ph ^= 1;

            if (DUAL) {
                stageA<K, KP>(sA, A2, row0, nrows, t);
                __syncthreads();
                if (wid == 0) {
                    if (elect1()) {
                        fence_async_proxy();
                        #pragma unroll 1
                        for (int c = 0; c < NCH; c++) {
                            uint64_t ad = descA  + (uint32_t)((c >> 2) * 1024 + (c & 3) * 2);
                            uint64_t bd = descB2 + (uint32_t)((c >> 2) * BSTRIDE + (c & 3) * 2);
                            mma_f16_ss(tmem, ad, bd, idesc, true);
                        }
                        mma_commit(mbar);
                    }
                }
                mbar_wait(mbar, ph); ph ^= 1;
            }

            // epilogue: warps 0-3 read D rows (lane = row within subpartition)
            if (wid < 4) {
                tc_fence_after();
                const int gr = row0 + wid * 32 + lane;
                #pragma unroll 1
                for (int cb = 0; cb < NCTA / 32; cb++) {
                    uint32_t r[32];
                    ldtm32(r, tmem + cb * 32);
                    tc_wait_ld();
                    tc_fence_before();
                    if (gr < nrows) {
                        const int cbase = half * NCTA + cb * 32;
                        #pragma unroll
                        for (int j = 0; j < 32; j += 4) {
                            float4 o;
                            o.x = __uint_as_float(r[j])     + sb[cbase + j];
                            o.y = __uint_as_float(r[j + 1]) + sb[cbase + j + 1];
                            o.z = __uint_as_float(r[j + 2]) + sb[cbase + j + 2];
                            o.w = __uint_as_float(r[j + 3]) + sb[cbase + j + 3];
                            if (RELU) {
                                o.x = fmaxf(o.x, 0.f); o.y = fmaxf(o.y, 0.f);
                                o.z = fmaxf(o.z, 0.f); o.w = fmaxf(o.w, 0.f);
                            }
                            *(float4*)&Y[gr * H + cbase + j] = o;
                        }
                    }
                }
            }
            __syncthreads();   // TMEM free + smem free before next tile
        }
    }

    if (t == 0) mbar_inval(mbar);
    __syncthreads();
    if (wid == 0) tmem_dealloc(tmem, 128);
}

// ---------------- edge scatter ----------------
__global__ void __launch_bounds__(NT) scatter_kernel(const int* __restrict__ edges) {
    int gtid = blockIdx.x * blockDim.x + threadIdx.x;
    int e = gtid >> 5;
    if (e >= N_EDGE) return;
    int lane = threadIdx.x & 31;
    int src = edges[e];
    int dst = edges[N_EDGE + e];
    float4 v = *(const float4*)&d_g[src * H + lane * 4];
    float* p = &d_agg[dst * H + lane * 4];
    asm volatile("red.global.add.v4.f32 [%0], {%1,%2,%3,%4};"
                 :: "l"(p), "f"(v.x), "f"(v.y), "f"(v.z), "f"(v.w)
                 : "memory");
}

// ---------------- final FC: out = p2 @ Wfc + bfc ----------------
__global__ void __launch_bounds__(NT) fc_kernel(const float* __restrict__ P,
                                                const float* __restrict__ Wfc,
                                                const float* __restrict__ bfc,
                                                float* __restrict__ out)
{
    __shared__ float sW[H * OUT];
    __shared__ float sbf[OUT];
    int t = threadIdx.x;
    for (int i = t; i < H * OUT; i += NT) sW[i] = Wfc[i];
    if (t < OUT) sbf[t] = bfc[t];
    __syncthreads();
    int idx = blockIdx.x * NT + t;
    int r = idx >> 2, q = idx & 3;
    if (r >= N_PATIENT) return;
    float s0 = sbf[2 * q], s1 = sbf[2 * q + 1];
    #pragma unroll 8
    for (int c4 = 0; c4 < H / 4; c4++) {
        float4 a = *(const float4*)&P[r * H + c4 * 4];
        s0 += a.x * sW[(c4*4    ) * OUT + 2*q];  s1 += a.x * sW[(c4*4    ) * OUT + 2*q + 1];
        s0 += a.y * sW[(c4*4 + 1) * OUT + 2*q];  s1 += a.y * sW[(c4*4 + 1) * OUT + 2*q + 1];
        s0 += a.z * sW[(c4*4 + 2) * OUT + 2*q];  s1 += a.z * sW[(c4*4 + 2) * OUT + 2*q + 1];
        s0 += a.w * sW[(c4*4 + 3) * OUT + 2*q];  s1 += a.w * sW[(c4*4 + 3) * OUT + 2*q + 1];
    }
    out[r * OUT + 2 * q]     = s0;
    out[r * OUT + 2 * q + 1] = s1;
}

// ---------------- launch ----------------
extern "C" void kernel_launch(void* const* d_in, const int* in_sizes, int n_in,
                              void* d_out, int out_size)
{
    const float* x_p  = (const float*)d_in[0];
    const float* x_g  = (const float*)d_in[1];
    const int*   eidx = (const int*)  d_in[2];
    const float* W_p1 = (const float*)d_in[3];
    const float* b_p1 = (const float*)d_in[4];
    const float* W_p2 = (const float*)d_in[5];
    const float* b_p2 = (const float*)d_in[6];
    const float* W_g1 = (const float*)d_in[7];
    const float* b_g1 = (const float*)d_in[8];
    const float* W_g2 = (const float*)d_in[9];
    const float* b_g2 = (const float*)d_in[10];
    const float* W1_l = (const float*)d_in[11];
    const float* b1_l = (const float*)d_in[12];
    const float* W1_r = (const float*)d_in[13];
    const float* W2_l = (const float*)d_in[14];
    const float* b2_l = (const float*)d_in[15];
    const float* W2_r = (const float*)d_in[16];
    const float* W_fc = (const float*)d_in[17];
    const float* b_fc = (const float*)d_in[18];
    float* out = (float*)d_out;

    float* g_g   = nullptr; cudaGetSymbolAddress((void**)&g_g,   d_g);
    float* g_agg = nullptr; cudaGetSymbolAddress((void**)&g_agg, d_agg);
    float* g_p   = nullptr; cudaGetSymbolAddress((void**)&g_p,   d_p);
    float* g_t   = nullptr; cudaGetSymbolAddress((void**)&g_t,   d_t);
    __nv_bfloat16* g_w = nullptr; cudaGetSymbolAddress((void**)&g_w, d_wsp);
    auto wsp = [&](int m) { return g_w + (size_t)m * H * 384; };

    // pass instantiations
    auto kG1 = mma_pass<32,  128, 128, false, true >;
    auto kP1 = mma_pass<64,  192, 128, false, true >;
    auto kL2 = mma_pass<128, 384, 128, false, false>;   // G2 & P2
    auto kS  = mma_pass<128, 384, 64,  true,  true >;   // S1 & S2

    const int smG1 = MTILE*128*2 + 128*128*2 + 1024;          // 66.5 KB
    const int smP1 = MTILE*192*2 + 128*192*2 + 1024;          // 99 KB
    const int smL2 = MTILE*384*2 + 128*384*2 + 1024;          // 197 KB
    const int smS  = MTILE*384*2 + 2*64*384*2 + 1024;         // 197 KB

    cudaFuncSetAttribute(kG1, cudaFuncAttributeMaxDynamicSharedMemorySize, smG1);
    cudaFuncSetAttribute(kP1, cudaFuncAttributeMaxDynamicSharedMemorySize, smP1);
    cudaFuncSetAttribute(kL2, cudaFuncAttributeMaxDynamicSharedMemorySize, smL2);
    cudaFuncSetAttribute(kS,  cudaFuncAttributeMaxDynamicSharedMemorySize, smS);

    // weight prep
    PrepArgs pa;
    pa.src[0] = W_g1; pa.K[0] = 32;  pa.KP[0] = 128;
    pa.src[1] = W_g2; pa.K[1] = 128; pa.KP[1] = 384;
    pa.src[2] = W_p1; pa.K[2] = 64;  pa.KP[2] = 192;
    pa.src[3] = W_p2; pa.K[3] = 128; pa.KP[3] = 384;
    pa.src[4] = W1_l; pa.K[4] = 128; pa.KP[4] = 384;
    pa.src[5] = W1_r; pa.K[5] = 128; pa.KP[5] = 384;
    pa.src[6] = W2_l; pa.K[6] = 128; pa.KP[6] = 384;
    pa.src[7] = W2_r; pa.K[7] = 128; pa.KP[7] = 384;

    const int zero_blocks    = (N_PATIENT * H / 4 + NT - 1) / NT;
    const int scatter_blocks = (N_EDGE * 32 + NT - 1) / NT;
    const int fc_blocks      = (N_PATIENT * 4 + NT - 1) / NT;

    zero_kernel<<<zero_blocks, NT>>>();
    prep_kernel<<<dim3((H * 384 + NT - 1) / NT, 8), NT>>>(pa);

    // gene MLP
    kG1<<<GRID_MMA, NT, smG1>>>(x_g, nullptr, wsp(0), nullptr, b_g1, g_t, N_GENE);
    kL2<<<GRID_MMA, NT, smL2>>>(g_t, nullptr, wsp(1), nullptr, b_g2, g_g, N_GENE);
    // patient MLP
    kP1<<<GRID_MMA, NT, smP1>>>(x_p, nullptr, wsp(2), nullptr, b_p1, g_t, N_PATIENT);
    kL2<<<GRID_MMA, NT, smL2>>>(g_t, nullptr, wsp(3), nullptr, b_p2, g_p, N_PATIENT);
    // aggregate
    scatter_kernel<<<scatter_blocks, NT>>>(eidx);
    // SAGE layers (dual-accumulate)
    kS<<<GRID_MMA, NT, smS>>>(g_agg, g_p, wsp(4), wsp(5), b1_l, g_t, N_PATIENT);
    kS<<<GRID_MMA, NT, smS>>>(g_agg, g_t, wsp(6), wsp(7), b2_l, g_p, N_PATIENT);
    // final FC
    fc_kernel<<<fc_blocks, NT>>>(g_p, W_fc, b_fc, out);
}

// round 15
// speedup vs baseline: 2.1005x; 1.1780x over previous
#include <cuda_runtime.h>
#include <cuda_bf16.h>
#include <cstdint>

#define N_PATIENT 50000
#define N_GENE    20000
#define N_EDGE    640000
#define P_DIM 64
#define G_DIM 32
#define H     128
#define OUT   8
#define NT    256
#define NTT   512
#define MTILE 128

#if defined(__CUDA_ARCH__) && (defined(__CUDA_ARCH_FEAT_SM103_ALL) || \
    defined(__CUDA_ARCH_FEAT_SM100_ALL) || defined(__CUDA_ARCH_FEAT_SM101_ALL))
#define HAS_TC5 1
#else
#define HAS_TC5 0
#endif

// ---------------- device scratch ----------------
__device__ float d_g  [N_GENE    * H];
__device__ float d_agg[N_PATIENT * H];
__device__ float d_p  [N_PATIENT * H];
__device__ float d_t  [N_PATIENT * H];
__device__ __nv_bfloat16 d_wsp[8][H * 256];   // dedup split weights [H][2K]

// ---------------- ptx helpers ----------------
__device__ __forceinline__ uint32_t cvta_s(const void* p) {
    uint32_t a;
    asm("{.reg .u64 t; cvta.to.shared.u64 t, %1; cvt.u32.u64 %0, t;}" : "=r"(a) : "l"(p));
    return a;
}
__device__ __forceinline__ bool elect1() {
    uint32_t p;
    asm volatile("{.reg .pred p; elect.sync _|p, 0xFFFFFFFF; selp.b32 %0,1,0,p;}" : "=r"(p));
    return p != 0;
}
__device__ __forceinline__ void sts128(uint32_t addr, uint32_t a, uint32_t b,
                                       uint32_t c, uint32_t d) {
    asm volatile("st.shared.v4.b32 [%0], {%1,%2,%3,%4};"
                 :: "r"(addr), "r"(a), "r"(b), "r"(c), "r"(d) : "memory");
}
__device__ __forceinline__ void mbar_init(uint32_t addr, uint32_t cnt) {
    asm volatile("mbarrier.init.shared.b64 [%0], %1;" :: "r"(addr), "r"(cnt) : "memory");
}
__device__ __forceinline__ void mbar_inval(uint32_t addr) {
    asm volatile("mbarrier.inval.shared.b64 [%0];" :: "r"(addr) : "memory");
}
__device__ __forceinline__ void mbar_wait(uint32_t mbar, uint32_t parity) {
    uint32_t done;
    asm volatile(
        "{\n\t.reg .pred p;\n\t"
        "mbarrier.try_wait.parity.acquire.cta.shared::cta.b64 p, [%1], %2;\n\t"
        "selp.b32 %0, 1, 0, p;\n\t}"
        : "=r"(done) : "r"(mbar), "r"(parity) : "memory");
    if (!done) {
        asm volatile(
            "{\n\t.reg .pred P1;\n\t"
            "WAIT_LOOP_%=:\n\t"
            "mbarrier.try_wait.parity.acquire.cta.shared::cta.b64 P1, [%0], %1, 0x989680;\n\t"
            "@P1 bra.uni WAIT_DONE_%=;\n\t"
            "bra.uni WAIT_LOOP_%=;\n\t"
            "WAIT_DONE_%=:\n\t}"
            :: "r"(mbar), "r"(parity) : "memory");
    }
}
__device__ __forceinline__ void tmem_alloc(uint32_t dst_smem, uint32_t ncols) {
#if HAS_TC5
    asm volatile("tcgen05.alloc.cta_group::1.sync.aligned.shared::cta.b32 [%0], %1;"
                 :: "r"(dst_smem), "r"(ncols) : "memory");
#endif
}
__device__ __forceinline__ void tmem_dealloc(uint32_t tmem, uint32_t ncols) {
#if HAS_TC5
    asm volatile("tcgen05.dealloc.cta_group::1.sync.aligned.b32 %0, %1;" :: "r"(tmem), "r"(ncols));
#endif
}
__device__ __forceinline__ void mma_f16_ss(uint32_t d_tmem, uint64_t a_desc,
                                           uint64_t b_desc, uint32_t idesc, bool en) {
#if HAS_TC5
    uint32_t e = en ? 1u : 0u;
    asm volatile(
        "{\n\t.reg .pred p;\n\t"
        "setp.ne.u32 p, %5, 0;\n\t"
        "tcgen05.mma.cta_group::1.kind::f16 [%0], %1, %2, %3, {%4,%4,%4,%4}, p;\n\t}"
        :: "r"(d_tmem), "l"(a_desc), "l"(b_desc), "r"(idesc), "r"(0u), "r"(e)
        : "memory");
#endif
}
__device__ __forceinline__ void mma_commit(uint32_t mbar) {
#if HAS_TC5
    asm volatile("tcgen05.commit.cta_group::1.mbarrier::arrive::one.shared::cluster.b64 [%0];"
                 :: "r"(mbar) : "memory");
#else
    asm volatile("mbarrier.arrive.shared.b64 _, [%0];" :: "r"(mbar) : "memory");
#endif
}
__device__ __forceinline__ void fence_async_proxy() {
    asm volatile("fence.proxy.async.shared::cta;" ::: "memory");
}
__device__ __forceinline__ void tc_fence_after() {
#if HAS_TC5
    asm volatile("tcgen05.fence::after_thread_sync;" ::: "memory");
#endif
}
__device__ __forceinline__ void tc_fence_before() {
#if HAS_TC5
    asm volatile("tcgen05.fence::before_thread_sync;" ::: "memory");
#endif
}
__device__ __forceinline__ void tc_wait_ld() {
#if HAS_TC5
    asm volatile("tcgen05.wait::ld.sync.aligned;" ::: "memory");
#endif
}
__device__ __forceinline__ void ldtm32(uint32_t* r, uint32_t tmem_addr) {
#if HAS_TC5
    asm volatile(
        "tcgen05.ld.sync.aligned.32x32b.x32.b32 "
        "{%0, %1, %2, %3, %4, %5, %6, %7, "
        " %8, %9, %10, %11, %12, %13, %14, %15, "
        " %16, %17, %18, %19, %20, %21, %22, %23, "
        " %24, %25, %26, %27, %28, %29, %30, %31}, [%32];"
        : "=r"(r[0]),  "=r"(r[1]),  "=r"(r[2]),  "=r"(r[3]),
          "=r"(r[4]),  "=r"(r[5]),  "=r"(r[6]),  "=r"(r[7]),
          "=r"(r[8]),  "=r"(r[9]),  "=r"(r[10]), "=r"(r[11]),
          "=r"(r[12]), "=r"(r[13]), "=r"(r[14]), "=r"(r[15]),
          "=r"(r[16]), "=r"(r[17]), "=r"(r[18]), "=r"(r[19]),
          "=r"(r[20]), "=r"(r[21]), "=r"(r[22]), "=r"(r[23]),
          "=r"(r[24]), "=r"(r[25]), "=r"(r[26]), "=r"(r[27]),
          "=r"(r[28]), "=r"(r[29]), "=r"(r[30]), "=r"(r[31])
        : "r"(tmem_addr));
#else
    for (int i = 0; i < 32; i++) r[i] = 0u;
#endif
}

static constexpr uint64_t DESC_BASE =
    (2ull << 61) | (1ull << 46) | (64ull << 32) | (1ull << 16);
__device__ __forceinline__ uint64_t make_desc(uint32_t addr) {
    return DESC_BASE | ((uint64_t)(addr >> 4) & 0x3FFF);
}
__device__ __forceinline__ uint32_t swz(uint32_t off) { return off ^ ((off >> 3) & 0x70); }
__device__ __forceinline__ uint32_t coff(int c) { return (c >> 2) * 1024 + (c & 3) * 2; }

// ---------------- zero agg ----------------
__global__ void __launch_bounds__(NT) zero_kernel() {
    int i = blockIdx.x * blockDim.x + threadIdx.x;
    const int n4 = N_PATIENT * H / 4;
    if (i < n4) ((float4*)d_agg)[i] = make_float4(0.f, 0.f, 0.f, 0.f);
}

// ---------------- weight split prep: W[K][H] f32 -> W'[H][2K] bf16 ([W0,W1]) ----
struct PrepArgs { const float* src[8]; int K[8]; };
__global__ void __launch_bounds__(NT) prep_kernel(PrepArgs a) {
    int m = blockIdx.y;
    int K = a.K[m], KP = 2 * K;
    const float* W = a.src[m];
    __nv_bfloat16* D = d_wsp[m];
    int i = blockIdx.x * blockDim.x + threadIdx.x;
    if (i >= H * KP) return;
    int c = i / KP, s = i % KP;
    __nv_bfloat16 v;
    if (s < K) {
        v = __float2bfloat16(W[s * H + c]);
    } else {
        float w = W[(s - K) * H + c];
        float w0 = __bfloat162float(__float2bfloat16(w));
        v = __float2bfloat16(w - w0);
    }
    D[c * KP + s] = v;
}

// ---------------- staging ----------------
__device__ __forceinline__ uint32_t offA(int row, int s) {
    return ((row >> 3) + (s >> 6) * 16) * 1024 + (row & 7) * 128 + (s & 63) * 2;
}
template<int K>
__device__ __forceinline__ void stageA(uint32_t sA, const float* __restrict__ A,
                                       int row0, int nrows, int t) {
    const int GP = K / 8;
    for (int g = t; g < MTILE * GP; g += NTT) {
        int row = g / GP, k8 = g % GP;
        int gr = row0 + row;
        float4 v0 = make_float4(0.f,0.f,0.f,0.f), v1 = v0;
        if (gr < nrows) {
            const float4* src = (const float4*)&A[gr * K + k8 * 8];
            v0 = src[0]; v1 = src[1];
        }
        float f[8] = {v0.x, v0.y, v0.z, v0.w, v1.x, v1.y, v1.z, v1.w};
        uint32_t p0[4], p1[4];
        #pragma unroll
        for (int j = 0; j < 4; j++) {
            __nv_bfloat16 b0 = __float2bfloat16(f[2*j]);
            __nv_bfloat16 b1 = __float2bfloat16(f[2*j+1]);
            __nv_bfloat162 q0 = __halves2bfloat162(b0, b1);
            p0[j] = *(uint32_t*)&q0;
            __nv_bfloat16 c0 = __float2bfloat16(f[2*j]   - __bfloat162float(b0));
            __nv_bfloat16 c1 = __float2bfloat16(f[2*j+1] - __bfloat162float(b1));
            __nv_bfloat162 q1 = __halves2bfloat162(c0, c1);
            p1[j] = *(uint32_t*)&q1;
        }
        int s = k8 * 8;
        sts128(sA + swz(offA(row, s)),     p0[0], p0[1], p0[2], p0[3]);
        sts128(sA + swz(offA(row, K + s)), p1[0], p1[1], p1[2], p1[3]);
    }
}
template<int K>
__device__ __forceinline__ void stageB(uint32_t sB, const __nv_bfloat16* __restrict__ Wp, int t) {
    const int KP = 2 * K, GP = KP / 8;
    const uint4* src = (const uint4*)Wp;
    for (int g = t; g < H * GP; g += NTT) {
        int r = g / GP, s8 = g % GP;
        uint4 v = src[g];
        sts128(sB + swz(offA(r, s8 * 8)), v.x, v.y, v.z, v.w);
    }
}

// 3-phase dedup MMA chain: D += A0*W0 + A0*W1 + A1*W0
template<int K>
__device__ __forceinline__ void issue_phases(uint32_t Dtm, uint64_t dA, uint64_t dB,
                                             uint32_t idesc, bool first) {
    const int K16 = K / 16;
    #pragma unroll 1
    for (int c = 0; c < K16; c++)
        mma_f16_ss(Dtm, dA + coff(c),       dB + coff(c),       idesc, !(first && c == 0));
    #pragma unroll 1
    for (int c = 0; c < K16; c++)
        mma_f16_ss(Dtm, dA + coff(c),       dB + coff(c + K16), idesc, true);
    #pragma unroll 1
    for (int c = 0; c < K16; c++)
        mma_f16_ss(Dtm, dA + coff(c + K16), dB + coff(c),       idesc, true);
}

// epilogue: 8 warps, full 128x128 f32 tile from TMEM + bias (+relu) -> Y
template<bool RELU>
__device__ __forceinline__ void epilogue(uint32_t Dtm, const float* sb,
                                         float* __restrict__ Y, int row0, int nrows,
                                         int wid, int lane) {
    if (wid >= 8) return;
    tc_fence_after();
    const int r = (wid & 3) * 32 + lane;
    const int gr = row0 + r;
    #pragma unroll 1
    for (int i = 0; i < 2; i++) {
        int cb = (wid >> 2) + i * 2;
        uint32_t rg[32];
        ldtm32(rg, Dtm + cb * 32);
        tc_wait_ld();
        tc_fence_before();
        if (gr < nrows) {
            const int cbase = cb * 32;
            #pragma unroll
            for (int j = 0; j < 32; j += 4) {
                float4 o;
                o.x = __uint_as_float(rg[j])     + sb[cbase + j];
                o.y = __uint_as_float(rg[j + 1]) + sb[cbase + j + 1];
                o.z = __uint_as_float(rg[j + 2]) + sb[cbase + j + 2];
                o.w = __uint_as_float(rg[j + 3]) + sb[cbase + j + 3];
                if (RELU) {
                    o.x = fmaxf(o.x, 0.f); o.y = fmaxf(o.y, 0.f);
                    o.z = fmaxf(o.z, 0.f); o.w = fmaxf(o.w, 0.f);
                }
                *(float4*)&Y[gr * H + cbase + j] = o;
            }
        }
    }
}

static constexpr uint32_t IDESC_BF16 =
    (1u << 4) | (1u << 7) | (1u << 10) | (16u << 17) | (8u << 24);

// ---------------- pipelined single-operand pass ----------------
// Y = [relu](A @ W + bias); A double-buffered, TMEM D double-buffered.
// Per-buffer mbarriers: each alternates commit->wait strictly (parity-safe).
template<int K, bool RELU, int MINB>
__global__ void __launch_bounds__(NTT, MINB) __cluster_dims__(1, 1, 1)
mma_pass(const float* __restrict__ A, const __nv_bfloat16* __restrict__ Wp,
         const float* __restrict__ bias, float* __restrict__ Y, int nrows)
{
    extern __shared__ char smx[];
    __shared__ uint32_t s_tmemptr;
    __shared__ __align__(8) unsigned long long s_mbar[2];
    __shared__ float sb[H];

    const int t = threadIdx.x, lane = t & 31, wid = t >> 5;
    const uint32_t mb[2] = {cvta_s(&s_mbar[0]), cvta_s(&s_mbar[1])};
    const uint32_t A_BYTES = MTILE * 2 * K * 2;
    uint32_t sA0 = (cvta_s(smx) + 1023u) & ~1023u;
    uint32_t sA1 = sA0 + A_BYTES;
    uint32_t sB  = sA1 + A_BYTES;

    if (wid == 0) tmem_alloc(cvta_s(&s_tmemptr), 256);
    if (t == 0) { mbar_init(mb[0], 1); mbar_init(mb[1], 1); }
    if (t < H) sb[t] = bias[t];
    stageB<K>(sB, Wp, t);
    __syncthreads();
    const uint32_t tmem = s_tmemptr;
    const uint64_t dB = make_desc(sB);
    const uint64_t dA[2] = {make_desc(sA0), make_desc(sA1)};
    const uint32_t sAb[2] = {sA0, sA1};

    const int ntiles = (nrows + MTILE - 1) / MTILE;
    uint32_t phb[2] = {0, 0};

    int t0 = blockIdx.x;
    if (t0 < ntiles) {
        stageA<K>(sA0, A, t0 * MTILE, nrows, t);
        __syncthreads();
        if (wid == 0 && elect1()) {
            fence_async_proxy();
            issue_phases<K>(tmem, dA[0], dB, IDESC_BF16, true);
            mma_commit(mb[0]);
        }
    }
    int prev = t0, pbuf = 0;
    #pragma unroll 1
    for (int tl = t0 + gridDim.x; tl < ntiles; tl += gridDim.x) {
        int cbuf = pbuf ^ 1;
        stageA<K>(sAb[cbuf], A, tl * MTILE, nrows, t);
        __syncthreads();
        if (wid == 0 && elect1()) {
            fence_async_proxy();
            issue_phases<K>(tmem + cbuf * 128, dA[cbuf], dB, IDESC_BF16, true);
            mma_commit(mb[cbuf]);
        }
        mbar_wait(mb[pbuf], phb[pbuf]); phb[pbuf] ^= 1;   // mma(prev) done
        epilogue<RELU>(tmem + pbuf * 128, sb, Y, prev * MTILE, nrows, wid, lane);
        __syncthreads();   // sA[pbuf] safe to restage next iteration
        prev = tl; pbuf = cbuf;
    }
    if (t0 < ntiles) {
        mbar_wait(mb[pbuf], phb[pbuf]); phb[pbuf] ^= 1;
        epilogue<RELU>(tmem + pbuf * 128, sb, Y, prev * MTILE, nrows, wid, lane);
    }

    __syncthreads();
    if (t == 0) { mbar_inval(mb[0]); mbar_inval(mb[1]); }
    __syncthreads();
    if (wid == 0) tmem_dealloc(tmem, 256);
}

// ---------------- dual-operand SAGE pass ----------------
// Y = relu(A1@W1 + A2@W2 + bias); single A buffer (staged twice), D double-buffered.
// Single mbarrier is parity-safe here: commits and waits strictly alternate.
__global__ void __launch_bounds__(NTT, 1) __cluster_dims__(1, 1, 1)
mma_sage(const float* __restrict__ A1, const float* __restrict__ A2,
         const __nv_bfloat16* __restrict__ W1p, const __nv_bfloat16* __restrict__ W2p,
         const float* __restrict__ bias, float* __restrict__ Y, int nrows)
{
    extern __shared__ char smx[];
    __shared__ uint32_t s_tmemptr;
    __shared__ __align__(8) unsigned long long s_mbar;
    __shared__ float sb[H];

    const int t = threadIdx.x, lane = t & 31, wid = t >> 5;
    const uint32_t mbar = cvta_s(&s_mbar);
    const uint32_t A_BYTES = MTILE * 256 * 2;
    uint32_t sA  = (cvta_s(smx) + 1023u) & ~1023u;
    uint32_t sB1 = sA + A_BYTES;
    uint32_t sB2 = sB1 + H * 256 * 2;

    if (wid == 0) tmem_alloc(cvta_s(&s_tmemptr), 256);
    if (t == 0) mbar_init(mbar, 1);
    if (t < H) sb[t] = bias[t];
    stageB<H>(sB1, W1p, t);
    stageB<H>(sB2, W2p, t);
    __syncthreads();
    const uint32_t tmem = s_tmemptr;
    const uint64_t dA  = make_desc(sA);
    const uint64_t dB1 = make_desc(sB1);
    const uint64_t dB2 = make_desc(sB2);

    const int ntiles = (nrows + MTILE - 1) / MTILE;
    uint32_t ph = 0;
    int prevRow0 = 0, pbuf = 0;
    bool havePrev = false;

    #pragma unroll 1
    for (int tl = blockIdx.x; tl < ntiles; tl += gridDim.x) {
        const int cbuf = havePrev ? (pbuf ^ 1) : 0;
        if (havePrev) { mbar_wait(mbar, ph); ph ^= 1; __syncthreads(); }  // mma2(prev) done -> A free
        stageA<H>(sA, A1, tl * MTILE, nrows, t);
        __syncthreads();
        if (wid == 0 && elect1()) {
            fence_async_proxy();
            issue_phases<H>(tmem + cbuf * 128, dA, dB1, IDESC_BF16, true);
            mma_commit(mbar);
        }
        if (havePrev)                                      // overlap mma1(cur)
            epilogue<true>(tmem + pbuf * 128, sb, Y, prevRow0, nrows, wid, lane);
        mbar_wait(mbar, ph); ph ^= 1;                      // mma1(cur) done -> A free
        __syncthreads();
        stageA<H>(sA, A2, tl * MTILE, nrows, t);
        __syncthreads();
        if (wid == 0 && elect1()) {
            fence_async_proxy();
            issue_phases<H>(tmem + cbuf * 128, dA, dB2, IDESC_BF16, false);  // accumulate
            mma_commit(mbar);
        }
        prevRow0 = tl * MTILE; pbuf = cbuf; havePrev = true;
    }
    if (havePrev) {
        mbar_wait(mbar, ph); ph ^= 1;
        epilogue<true>(tmem + pbuf * 128, sb, Y, prevRow0, nrows, wid, lane);
    }

    __syncthreads();
    if (t == 0) mbar_inval(mbar);
    __syncthreads();
    if (wid == 0) tmem_dealloc(tmem, 256);
}

// ---------------- edge scatter ----------------
__global__ void __launch_bounds__(NT) scatter_kernel(const int* __restrict__ edges) {
    int gtid = blockIdx.x * blockDim.x + threadIdx.x;
    int e = gtid >> 5;
    if (e >= N_EDGE) return;
    int lane = threadIdx.x & 31;
    int src = edges[e];
    int dst = edges[N_EDGE + e];
    float4 v = *(const float4*)&d_g[src * H + lane * 4];
    float* p = &d_agg[dst * H + lane * 4];
    asm volatile("red.global.add.v4.f32 [%0], {%1,%2,%3,%4};"
                 :: "l"(p), "f"(v.x), "f"(v.y), "f"(v.z), "f"(v.w)
                 : "memory");
}

// ---------------- final FC ----------------
__global__ void __launch_bounds__(NT) fc_kernel(const float* __restrict__ P,
                                                const float* __restrict__ Wfc,
                                                const float* __restrict__ bfc,
                                                float* __restrict__ out)
{
    __shared__ float sW[H * OUT];
    __shared__ float sbf[OUT];
    int t = threadIdx.x;
    for (int i = t; i < H * OUT; i += NT) sW[i] = Wfc[i];
    if (t < OUT) sbf[t] = bfc[t];
    __syncthreads();
    int idx = blockIdx.x * NT + t;
    int r = idx >> 2, q = idx & 3;
    if (r >= N_PATIENT) return;
    float s0 = sbf[2 * q], s1 = sbf[2 * q + 1];
    #pragma unroll 8
    for (int c4 = 0; c4 < H / 4; c4++) {
        float4 a = *(const float4*)&P[r * H + c4 * 4];
        s0 += a.x * sW[(c4*4    ) * OUT + 2*q];  s1 += a.x * sW[(c4*4    ) * OUT + 2*q + 1];
        s0 += a.y * sW[(c4*4 + 1) * OUT + 2*q];  s1 += a.y * sW[(c4*4 + 1) * OUT + 2*q + 1];
        s0 += a.z * sW[(c4*4 + 2) * OUT + 2*q];  s1 += a.z * sW[(c4*4 + 2) * OUT + 2*q + 1];
        s0 += a.w * sW[(c4*4 + 3) * OUT + 2*q];  s1 += a.w * sW[(c4*4 + 3) * OUT + 2*q + 1];
    }
    out[r * OUT + 2 * q]     = s0;
    out[r * OUT + 2 * q + 1] = s1;
}

// ---------------- launch ----------------
extern "C" void kernel_launch(void* const* d_in, const int* in_sizes, int n_in,
                              void* d_out, int out_size)
{
    const float* x_p  = (const float*)d_in[0];
    const float* x_g  = (const float*)d_in[1];
    const int*   eidx = (const int*)  d_in[2];
    const float* W_p1 = (const float*)d_in[3];
    const float* b_p1 = (const float*)d_in[4];
    const float* W_p2 = (const float*)d_in[5];
    const float* b_p2 = (const float*)d_in[6];
    const float* W_g1 = (const float*)d_in[7];
    const float* b_g1 = (const float*)d_in[8];
    const float* W_g2 = (const float*)d_in[9];
    const float* b_g2 = (const float*)d_in[10];
    const float* W1_l = (const float*)d_in[11];
    const float* b1_l = (const float*)d_in[12];
    const float* W1_r = (const float*)d_in[13];
    const float* W2_l = (const float*)d_in[14];
    const float* b2_l = (const float*)d_in[15];
    const float* W2_r = (const float*)d_in[16];
    const float* W_fc = (const float*)d_in[17];
    const float* b_fc = (const float*)d_in[18];
    float* out = (float*)d_out;

    float* g_g   = nullptr; cudaGetSymbolAddress((void**)&g_g,   d_g);
    float* g_agg = nullptr; cudaGetSymbolAddress((void**)&g_agg, d_agg);
    float* g_p   = nullptr; cudaGetSymbolAddress((void**)&g_p,   d_p);
    float* g_t   = nullptr; cudaGetSymbolAddress((void**)&g_t,   d_t);
    __nv_bfloat16* g_w = nullptr; cudaGetSymbolAddress((void**)&g_w, d_wsp);
    auto wsp = [&](int m) { return g_w + (size_t)m * H * 256; };

    auto kG1 = mma_pass<G_DIM, true,  2>;
    auto kP1 = mma_pass<P_DIM, true,  2>;
    auto kL2 = mma_pass<H,     false, 1>;

    const int smG1 = 2*(MTILE*64*2)  + H*64*2  + 1024;   //  49 KB
    const int smP1 = 2*(MTILE*128*2) + H*128*2 + 1024;   //  97 KB
    const int smL2 = 2*(MTILE*256*2) + H*256*2 + 1024;   // 193 KB
    const int smS  = MTILE*256*2 + 2*(H*256*2) + 1024;   // 193 KB

    cudaFuncSetAttribute(kG1, cudaFuncAttributeMaxDynamicSharedMemorySize, smG1);
    cudaFuncSetAttribute(kP1, cudaFuncAttributeMaxDynamicSharedMemorySize, smP1);
    cudaFuncSetAttribute(kL2, cudaFuncAttributeMaxDynamicSharedMemorySize, smL2);
    cudaFuncSetAttribute(mma_sage, cudaFuncAttributeMaxDynamicSharedMemorySize, smS);

    PrepArgs pa;
    pa.src[0] = W_g1; pa.K[0] = 32;
    pa.src[1] = W_g2; pa.K[1] = 128;
    pa.src[2] = W_p1; pa.K[2] = 64;
    pa.src[3] = W_p2; pa.K[3] = 128;
    pa.src[4] = W1_l; pa.K[4] = 128;
    pa.src[5] = W1_r; pa.K[5] = 128;
    pa.src[6] = W2_l; pa.K[6] = 128;
    pa.src[7] = W2_r; pa.K[7] = 128;

    const int zero_blocks    = (N_PATIENT * H / 4 + NT - 1) / NT;
    const int scatter_blocks = (N_EDGE * 32 + NT - 1) / NT;
    const int fc_blocks      = (N_PATIENT * 4 + NT - 1) / NT;
    const int gtiles = (N_GENE + MTILE - 1) / MTILE;       // 157

    zero_kernel<<<zero_blocks, NT>>>();
    prep_kernel<<<dim3((H * 256 + NT - 1) / NT, 8), NT>>>(pa);

    // gene MLP
    kG1<<<gtiles, NTT, smG1>>>(x_g, wsp(0), b_g1, g_t, N_GENE);
    kL2<<<148,    NTT, smL2>>>(g_t, wsp(1), b_g2, g_g, N_GENE);
    // patient MLP
    kP1<<<296, NTT, smP1>>>(x_p, wsp(2), b_p1, g_t, N_PATIENT);
    kL2<<<148, NTT, smL2>>>(g_t, wsp(3), b_p2, g_p, N_PATIENT);
    // aggregate
    scatter_kernel<<<scatter_blocks, NT>>>(eidx);
    // SAGE layers
    mma_sage<<<148, NTT, smS>>>(g_agg, g_p, wsp(4), wsp(5), b1_l, g_t, N_PATIENT);
    mma_sage<<<148, NTT, smS>>>(g_agg, g_t, wsp(6), wsp(7), b2_l, g_p, N_PATIENT);
    // final FC
    fc_kernel<<<fc_blocks, NT>>>(g_p, W_fc, b_fc, out);
}

// round 16
// speedup vs baseline: 2.1599x; 1.0282x over previous
#include <cuda_runtime.h>
#include <cuda_bf16.h>
#include <cstdint>

#define N_PATIENT 50000
#define N_GENE    20000
#define N_EDGE    640000
#define P_DIM 64
#define G_DIM 32
#define H     128
#define OUT   8
#define NT    256
#define NTT   512
#define MTILE 128

#if defined(__CUDA_ARCH__) && (defined(__CUDA_ARCH_FEAT_SM103_ALL) || \
    defined(__CUDA_ARCH_FEAT_SM100_ALL) || defined(__CUDA_ARCH_FEAT_SM101_ALL))
#define HAS_TC5 1
#else
#define HAS_TC5 0
#endif

// ---------------- device scratch ----------------
__device__ float d_g  [N_GENE    * H];
__device__ float d_agg[N_PATIENT * H];
__device__ float d_p  [N_PATIENT * H];
__device__ float d_t  [N_PATIENT * H];
__device__ __nv_bfloat16 d_wsp[8][H * 256];   // dedup split weights [H][2K]
__device__ int d_cnt[N_PATIENT];
__device__ int d_off[N_PATIENT + 1];
__device__ int d_pos[N_PATIENT];
__device__ int d_eid[N_EDGE];

// ---------------- ptx helpers ----------------
__device__ __forceinline__ uint32_t cvta_s(const void* p) {
    uint32_t a;
    asm("{.reg .u64 t; cvta.to.shared.u64 t, %1; cvt.u32.u64 %0, t;}" : "=r"(a) : "l"(p));
    return a;
}
__device__ __forceinline__ bool elect1() {
    uint32_t p;
    asm volatile("{.reg .pred p; elect.sync _|p, 0xFFFFFFFF; selp.b32 %0,1,0,p;}" : "=r"(p));
    return p != 0;
}
__device__ __forceinline__ void sts128(uint32_t addr, uint32_t a, uint32_t b,
                                       uint32_t c, uint32_t d) {
    asm volatile("st.shared.v4.b32 [%0], {%1,%2,%3,%4};"
                 :: "r"(addr), "r"(a), "r"(b), "r"(c), "r"(d) : "memory");
}
__device__ __forceinline__ void sts32(uint32_t addr, uint32_t v) {
    asm volatile("st.shared.b32 [%0], %1;" :: "r"(addr), "r"(v) : "memory");
}
__device__ __forceinline__ void mbar_init(uint32_t addr, uint32_t cnt) {
    asm volatile("mbarrier.init.shared.b64 [%0], %1;" :: "r"(addr), "r"(cnt) : "memory");
}
__device__ __forceinline__ void mbar_inval(uint32_t addr) {
    asm volatile("mbarrier.inval.shared.b64 [%0];" :: "r"(addr) : "memory");
}
__device__ __forceinline__ void mbar_wait(uint32_t mbar, uint32_t parity) {
    uint32_t done;
    asm volatile(
        "{\n\t.reg .pred p;\n\t"
        "mbarrier.try_wait.parity.acquire.cta.shared::cta.b64 p, [%1], %2;\n\t"
        "selp.b32 %0, 1, 0, p;\n\t}"
        : "=r"(done) : "r"(mbar), "r"(parity) : "memory");
    if (!done) {
        asm volatile(
            "{\n\t.reg .pred P1;\n\t"
            "WAIT_LOOP_%=:\n\t"
            "mbarrier.try_wait.parity.acquire.cta.shared::cta.b64 P1, [%0], %1, 0x989680;\n\t"
            "@P1 bra.uni WAIT_DONE_%=;\n\t"
            "bra.uni WAIT_LOOP_%=;\n\t"
            "WAIT_DONE_%=:\n\t}"
            :: "r"(mbar), "r"(parity) : "memory");
    }
}
__device__ __forceinline__ void tmem_alloc(uint32_t dst_smem, uint32_t ncols) {
#if HAS_TC5
    asm volatile("tcgen05.alloc.cta_group::1.sync.aligned.shared::cta.b32 [%0], %1;"
                 :: "r"(dst_smem), "r"(ncols) : "memory");
#endif
}
__device__ __forceinline__ void tmem_dealloc(uint32_t tmem, uint32_t ncols) {
#if HAS_TC5
    asm volatile("tcgen05.dealloc.cta_group::1.sync.aligned.b32 %0, %1;" :: "r"(tmem), "r"(ncols));
#endif
}
__device__ __forceinline__ void mma_f16_ss(uint32_t d_tmem, uint64_t a_desc,
                                           uint64_t b_desc, uint32_t idesc, bool en) {
#if HAS_TC5
    uint32_t e = en ? 1u : 0u;
    asm volatile(
        "{\n\t.reg .pred p;\n\t"
        "setp.ne.u32 p, %5, 0;\n\t"
        "tcgen05.mma.cta_group::1.kind::f16 [%0], %1, %2, %3, {%4,%4,%4,%4}, p;\n\t}"
        :: "r"(d_tmem), "l"(a_desc), "l"(b_desc), "r"(idesc), "r"(0u), "r"(e)
        : "memory");
#endif
}
__device__ __forceinline__ void mma_commit(uint32_t mbar) {
#if HAS_TC5
    asm volatile("tcgen05.commit.cta_group::1.mbarrier::arrive::one.shared::cluster.b64 [%0];"
                 :: "r"(mbar) : "memory");
#else
    asm volatile("mbarrier.arrive.shared.b64 _, [%0];" :: "r"(mbar) : "memory");
#endif
}
__device__ __forceinline__ void fence_async_proxy() {
    asm volatile("fence.proxy.async.shared::cta;" ::: "memory");
}
__device__ __forceinline__ void tc_fence_after() {
#if HAS_TC5
    asm volatile("tcgen05.fence::after_thread_sync;" ::: "memory");
#endif
}
__device__ __forceinline__ void tc_fence_before() {
#if HAS_TC5
    asm volatile("tcgen05.fence::before_thread_sync;" ::: "memory");
#endif
}
__device__ __forceinline__ void tc_wait_ld() {
#if HAS_TC5
    asm volatile("tcgen05.wait::ld.sync.aligned;" ::: "memory");
#endif
}
__device__ __forceinline__ void ldtm32(uint32_t* r, uint32_t tmem_addr) {
#if HAS_TC5
    asm volatile(
        "tcgen05.ld.sync.aligned.32x32b.x32.b32 "
        "{%0, %1, %2, %3, %4, %5, %6, %7, "
        " %8, %9, %10, %11, %12, %13, %14, %15, "
        " %16, %17, %18, %19, %20, %21, %22, %23, "
        " %24, %25, %26, %27, %28, %29, %30, %31}, [%32];"
        : "=r"(r[0]),  "=r"(r[1]),  "=r"(r[2]),  "=r"(r[3]),
          "=r"(r[4]),  "=r"(r[5]),  "=r"(r[6]),  "=r"(r[7]),
          "=r"(r[8]),  "=r"(r[9]),  "=r"(r[10]), "=r"(r[11]),
          "=r"(r[12]), "=r"(r[13]), "=r"(r[14]), "=r"(r[15]),
          "=r"(r[16]), "=r"(r[17]), "=r"(r[18]), "=r"(r[19]),
          "=r"(r[20]), "=r"(r[21]), "=r"(r[22]), "=r"(r[23]),
          "=r"(r[24]), "=r"(r[25]), "=r"(r[26]), "=r"(r[27]),
          "=r"(r[28]), "=r"(r[29]), "=r"(r[30]), "=r"(r[31])
        : "r"(tmem_addr));
#else
    for (int i = 0; i < 32; i++) r[i] = 0u;
#endif
}

static constexpr uint64_t DESC_BASE =
    (2ull << 61) | (1ull << 46) | (64ull << 32) | (1ull << 16);
__device__ __forceinline__ uint64_t make_desc(uint32_t addr) {
    return DESC_BASE | ((uint64_t)(addr >> 4) & 0x3FFF);
}
__device__ __forceinline__ uint32_t swz(uint32_t off) { return off ^ ((off >> 3) & 0x70); }
__device__ __forceinline__ uint32_t coff(int c) { return (c >> 2) * 1024 + (c & 3) * 2; }

// ---------------- weight split prep: W[K][H] f32 -> W'[H][2K] bf16 ([W0,W1]) ----
struct PrepArgs { const float* src[8]; int K[8]; };
__global__ void __launch_bounds__(NT) prep_kernel(PrepArgs a) {
    int m = blockIdx.y;
    int K = a.K[m], KP = 2 * K;
    const float* W = a.src[m];
    __nv_bfloat16* D = d_wsp[m];
    int i = blockIdx.x * blockDim.x + threadIdx.x;
    if (i >= H * KP) return;
    int c = i / KP, s = i % KP;
    __nv_bfloat16 v;
    if (s < K) {
        v = __float2bfloat16(W[s * H + c]);
    } else {
        float w = W[(s - K) * H + c];
        float w0 = __bfloat162float(__float2bfloat16(w));
        v = __float2bfloat16(w - w0);
    }
    D[c * KP + s] = v;
}

// ---------------- staging ----------------
__device__ __forceinline__ uint32_t offA(int row, int s) {
    return ((row >> 3) + (s >> 6) * 16) * 1024 + (row & 7) * 128 + (s & 63) * 2;
}
template<int K>
__device__ __forceinline__ void stageA(uint32_t sA, const float* __restrict__ A,
                                       int row0, int nrows, int t) {
    const int GP = K / 8;
    for (int g = t; g < MTILE * GP; g += NTT) {
        int row = g / GP, k8 = g % GP;
        int gr = row0 + row;
        float4 v0 = make_float4(0.f,0.f,0.f,0.f), v1 = v0;
        if (gr < nrows) {
            const float4* src = (const float4*)&A[gr * K + k8 * 8];
            v0 = src[0]; v1 = src[1];
        }
        float f[8] = {v0.x, v0.y, v0.z, v0.w, v1.x, v1.y, v1.z, v1.w};
        uint32_t p0[4], p1[4];
        #pragma unroll
        for (int j = 0; j < 4; j++) {
            __nv_bfloat16 b0 = __float2bfloat16(f[2*j]);
            __nv_bfloat16 b1 = __float2bfloat16(f[2*j+1]);
            __nv_bfloat162 q0 = __halves2bfloat162(b0, b1);
            p0[j] = *(uint32_t*)&q0;
            __nv_bfloat16 c0 = __float2bfloat16(f[2*j]   - __bfloat162float(b0));
            __nv_bfloat16 c1 = __float2bfloat16(f[2*j+1] - __bfloat162float(b1));
            __nv_bfloat162 q1 = __halves2bfloat162(c0, c1);
            p1[j] = *(uint32_t*)&q1;
        }
        int s = k8 * 8;
        sts128(sA + swz(offA(row, s)),     p0[0], p0[1], p0[2], p0[3]);
        sts128(sA + swz(offA(row, K + s)), p1[0], p1[1], p1[2], p1[3]);
    }
}
template<int K>
__device__ __forceinline__ void stageB(uint32_t sB, const __nv_bfloat16* __restrict__ Wp, int t) {
    const int KP = 2 * K, GP = KP / 8;
    const uint4* src = (const uint4*)Wp;
    for (int g = t; g < H * GP; g += NTT) {
        int r = g / GP, s8 = g % GP;
        uint4 v = src[g];
        sts128(sB + swz(offA(r, s8 * 8)), v.x, v.y, v.z, v.w);
    }
}

// 3-phase dedup MMA chain: D += A0*W0 + A0*W1 + A1*W0
template<int K>
__device__ __forceinline__ void issue_phases(uint32_t Dtm, uint64_t dA, uint64_t dB,
                                             uint32_t idesc, bool first) {
    const int K16 = K / 16;
    #pragma unroll 1
    for (int c = 0; c < K16; c++)
        mma_f16_ss(Dtm, dA + coff(c),       dB + coff(c),       idesc, !(first && c == 0));
    #pragma unroll 1
    for (int c = 0; c < K16; c++)
        mma_f16_ss(Dtm, dA + coff(c),       dB + coff(c + K16), idesc, true);
    #pragma unroll 1
    for (int c = 0; c < K16; c++)
        mma_f16_ss(Dtm, dA + coff(c + K16), dB + coff(c),       idesc, true);
}

// epilogue: 8 warps, full 128x128 f32 tile from TMEM + bias (+relu) -> Y (global)
template<bool RELU>
__device__ __forceinline__ void epilogue(uint32_t Dtm, const float* sb,
                                         float* __restrict__ Y, int row0, int nrows,
                                         int wid, int lane) {
    if (wid >= 8) return;
    tc_fence_after();
    const int r = (wid & 3) * 32 + lane;
    const int gr = row0 + r;
    #pragma unroll 1
    for (int i = 0; i < 2; i++) {
        int cb = (wid >> 2) + i * 2;
        uint32_t rg[32];
        ldtm32(rg, Dtm + cb * 32);
        tc_wait_ld();
        tc_fence_before();
        if (gr < nrows) {
            const int cbase = cb * 32;
            #pragma unroll
            for (int j = 0; j < 32; j += 4) {
                float4 o;
                o.x = __uint_as_float(rg[j])     + sb[cbase + j];
                o.y = __uint_as_float(rg[j + 1]) + sb[cbase + j + 1];
                o.z = __uint_as_float(rg[j + 2]) + sb[cbase + j + 2];
                o.w = __uint_as_float(rg[j + 3]) + sb[cbase + j + 3];
                if (RELU) {
                    o.x = fmaxf(o.x, 0.f); o.y = fmaxf(o.y, 0.f);
                    o.z = fmaxf(o.z, 0.f); o.w = fmaxf(o.w, 0.f);
                }
                *(float4*)&Y[gr * H + cbase + j] = o;
            }
        }
    }
}

// mid epilogue: TMEM -> bias+relu -> bf16 split -> SMEM A-tile (256 slots/row)
__device__ __forceinline__ void epilogue_to_smem(uint32_t Dtm, const float* sb,
                                                 uint32_t sA2, int wid, int lane) {
    if (wid >= 8) return;
    tc_fence_after();
    const int r = (wid & 3) * 32 + lane;
    #pragma unroll 1
    for (int i = 0; i < 2; i++) {
        int cb = (wid >> 2) + i * 2;
        uint32_t rg[32];
        ldtm32(rg, Dtm + cb * 32);
        tc_wait_ld();
        tc_fence_before();
        const int cbase = cb * 32;
        #pragma unroll
        for (int j = 0; j < 32; j += 2) {
            float v0 = fmaxf(__uint_as_float(rg[j])     + sb[cbase + j], 0.f);
            float v1 = fmaxf(__uint_as_float(rg[j + 1]) + sb[cbase + j + 1], 0.f);
            __nv_bfloat16 b0 = __float2bfloat16(v0);
            __nv_bfloat16 b1 = __float2bfloat16(v1);
            __nv_bfloat162 q0 = __halves2bfloat162(b0, b1);
            __nv_bfloat16 c0 = __float2bfloat16(v0 - __bfloat162float(b0));
            __nv_bfloat16 c1 = __float2bfloat16(v1 - __bfloat162float(b1));
            __nv_bfloat162 q1 = __halves2bfloat162(c0, c1);
            sts32(sA2 + swz(offA(r, cbase + j)),       *(uint32_t*)&q0);
            sts32(sA2 + swz(offA(r, 128 + cbase + j)), *(uint32_t*)&q1);
        }
    }
}

static constexpr uint32_t IDESC_BF16 =
    (1u << 4) | (1u << 7) | (1u << 10) | (16u << 17) | (8u << 24);

// ---------------- fused 2-layer MLP (tcgen05) ----------------
// Y = relu(X@W1+b1)@W2 + b2 ; layer-1 result never leaves SMEM.
template<int K1>
__global__ void __launch_bounds__(NTT, 1) __cluster_dims__(1, 1, 1)
mlp_fused(const float* __restrict__ X,
          const __nv_bfloat16* __restrict__ W1p, const float* __restrict__ b1,
          const __nv_bfloat16* __restrict__ W2p, const float* __restrict__ b2,
          float* __restrict__ Y, int nrows)
{
    extern __shared__ char smx[];
    __shared__ uint32_t s_tmemptr;
    __shared__ __align__(8) unsigned long long s_mbar;
    __shared__ float sb1[H], sb2[H];

    const int t = threadIdx.x, lane = t & 31, wid = t >> 5;
    const uint32_t mbar = cvta_s(&s_mbar);
    const uint32_t SZ1 = MTILE * 2 * K1 * 2;
    uint32_t sA1 = (cvta_s(smx) + 1023u) & ~1023u;
    uint32_t sB1 = sA1 + SZ1;
    uint32_t sA2 = sB1 + SZ1;
    uint32_t sB2 = sA2 + MTILE * 256 * 2;

    if (wid == 0) tmem_alloc(cvta_s(&s_tmemptr), 256);
    if (t == 0) mbar_init(mbar, 1);
    if (t < H) { sb1[t] = b1[t]; sb2[t] = b2[t]; }
    stageB<K1>(sB1, W1p, t);
    stageB<H>(sB2, W2p, t);
    __syncthreads();
    const uint32_t tmem = s_tmemptr;
    const uint64_t dA1 = make_desc(sA1), dB1 = make_desc(sB1);
    const uint64_t dA2 = make_desc(sA2), dB2 = make_desc(sB2);

    const int ntiles = (nrows + MTILE - 1) / MTILE;
    uint32_t ph = 0;

    #pragma unroll 1
    for (int tile = blockIdx.x; tile < ntiles; tile += gridDim.x) {
        const int row0 = tile * MTILE;
        stageA<K1>(sA1, X, row0, nrows, t);
        __syncthreads();
        if (wid == 0 && elect1()) {
            fence_async_proxy();
            issue_phases<K1>(tmem, dA1, dB1, IDESC_BF16, true);
            mma_commit(mbar);
        }
        mbar_wait(mbar, ph); ph ^= 1;
        epilogue_to_smem(tmem, sb1, sA2, wid, lane);    // h -> sA2 (bf16 split)
        __syncthreads();
        if (wid == 0 && elect1()) {
            fence_async_proxy();
            issue_phases<H>(tmem + 128, dA2, dB2, IDESC_BF16, true);
            mma_commit(mbar);
        }
        mbar_wait(mbar, ph); ph ^= 1;
        epilogue<false>(tmem + 128, sb2, Y, row0, nrows, wid, lane);
        __syncthreads();    // sA1/sA2 free before next tile
    }

    __syncthreads();
    if (t == 0) mbar_inval(mbar);
    __syncthreads();
    if (wid == 0) tmem_dealloc(tmem, 256);
}

// ---------------- dual-operand SAGE pass (unchanged from R14) ----------------
__global__ void __launch_bounds__(NTT, 1) __cluster_dims__(1, 1, 1)
mma_sage(const float* __restrict__ A1, const float* __restrict__ A2,
         const __nv_bfloat16* __restrict__ W1p, const __nv_bfloat16* __restrict__ W2p,
         const float* __restrict__ bias, float* __restrict__ Y, int nrows)
{
    extern __shared__ char smx[];
    __shared__ uint32_t s_tmemptr;
    __shared__ __align__(8) unsigned long long s_mbar;
    __shared__ float sb[H];

    const int t = threadIdx.x, lane = t & 31, wid = t >> 5;
    const uint32_t mbar = cvta_s(&s_mbar);
    const uint32_t A_BYTES = MTILE * 256 * 2;
    uint32_t sA  = (cvta_s(smx) + 1023u) & ~1023u;
    uint32_t sB1 = sA + A_BYTES;
    uint32_t sB2 = sB1 + H * 256 * 2;

    if (wid == 0) tmem_alloc(cvta_s(&s_tmemptr), 256);
    if (t == 0) mbar_init(mbar, 1);
    if (t < H) sb[t] = bias[t];
    stageB<H>(sB1, W1p, t);
    stageB<H>(sB2, W2p, t);
    __syncthreads();
    const uint32_t tmem = s_tmemptr;
    const uint64_t dA  = make_desc(sA);
    const uint64_t dB1 = make_desc(sB1);
    const uint64_t dB2 = make_desc(sB2);

    const int ntiles = (nrows + MTILE - 1) / MTILE;
    uint32_t ph = 0;
    int prevRow0 = 0, pbuf = 0;
    bool havePrev = false;

    #pragma unroll 1
    for (int tl = blockIdx.x; tl < ntiles; tl += gridDim.x) {
        const int cbuf = havePrev ? (pbuf ^ 1) : 0;
        if (havePrev) { mbar_wait(mbar, ph); ph ^= 1; __syncthreads(); }
        stageA<H>(sA, A1, tl * MTILE, nrows, t);
        __syncthreads();
        if (wid == 0 && elect1()) {
            fence_async_proxy();
            issue_phases<H>(tmem + cbuf * 128, dA, dB1, IDESC_BF16, true);
            mma_commit(mbar);
        }
        if (havePrev)
            epilogue<true>(tmem + pbuf * 128, sb, Y, prevRow0, nrows, wid, lane);
        mbar_wait(mbar, ph); ph ^= 1;
        __syncthreads();
        stageA<H>(sA, A2, tl * MTILE, nrows, t);
        __syncthreads();
        if (wid == 0 && elect1()) {
            fence_async_proxy();
            issue_phases<H>(tmem + cbuf * 128, dA, dB2, IDESC_BF16, false);
            mma_commit(mbar);
        }
        prevRow0 = tl * MTILE; pbuf = cbuf; havePrev = true;
    }
    if (havePrev) {
        mbar_wait(mbar, ph); ph ^= 1;
        epilogue<true>(tmem + pbuf * 128, sb, Y, prevRow0, nrows, wid, lane);
    }

    __syncthreads();
    if (t == 0) mbar_inval(mbar);
    __syncthreads();
    if (wid == 0) tmem_dealloc(tmem, 256);
}

// ---------------- CSR build + gather aggregation ----------------
__global__ void __launch_bounds__(NT) zero_cnt_kernel() {
    int i = blockIdx.x * blockDim.x + threadIdx.x;
    if (i < N_PATIENT) d_cnt[i] = 0;
}
__global__ void __launch_bounds__(NT) hist_kernel(const int* __restrict__ edges) {
    int e = blockIdx.x * blockDim.x + threadIdx.x;
    if (e < N_EDGE) atomicAdd(&d_cnt[edges[N_EDGE + e]], 1);
}
__global__ void __launch_bounds__(1024) scan_kernel() {
    __shared__ int wsum[32];
    __shared__ int s_run;
    const int t = threadIdx.x, lane = t & 31, wid = t >> 5;
    if (t == 0) s_run = 0;
    __syncthreads();
    for (int base = 0; base < N_PATIENT; base += 1024) {
        int v = (base + t < N_PATIENT) ? d_cnt[base + t] : 0;
        int x = v;
        #pragma unroll
        for (int d = 1; d < 32; d <<= 1) {
            int y = __shfl_up_sync(0xFFFFFFFF, x, d);
            if (lane >= d) x += y;
        }
        if (lane == 31) wsum[wid] = x;
        __syncthreads();
        if (t < 32) {
            int s = wsum[t];
            #pragma unroll
            for (int d = 1; d < 32; d <<= 1) {
                int y = __shfl_up_sync(0xFFFFFFFF, s, d);
                if (t >= d) s += y;
            }
            wsum[t] = s;
        }
        __syncthreads();
        int wbase = (wid == 0) ? 0 : wsum[wid - 1];
        int excl = s_run + wbase + (x - v);
        if (base + t < N_PATIENT) { d_off[base + t] = excl; d_pos[base + t] = excl; }
        __syncthreads();
        if (t == 0) s_run += wsum[31];
        __syncthreads();
    }
    if (threadIdx.x == 0) d_off[N_PATIENT] = s_run;
}
__global__ void __launch_bounds__(NT) fill_kernel(const int* __restrict__ edges) {
    int e = blockIdx.x * blockDim.x + threadIdx.x;
    if (e >= N_EDGE) return;
    int dst = edges[N_EDGE + e];
    int slot = atomicAdd(&d_pos[dst], 1);
    d_eid[slot] = edges[e];
}
// one warp per dst row: agg[dst] = sum over neighbors g[src] (no atomics)
__global__ void __launch_bounds__(NT) gather_kernel() {
    const int lane = threadIdx.x & 31;
    const int w = (blockIdx.x * blockDim.x + threadIdx.x) >> 5;
    const int nw = (gridDim.x * blockDim.x) >> 5;
    for (int dst = w; dst < N_PATIENT; dst += nw) {
        int beg = d_off[dst], end = d_off[dst + 1];
        float4 a0 = make_float4(0.f,0.f,0.f,0.f), a1 = a0, a2 = a0, a3 = a0;
        int i = beg;
        for (; i + 4 <= end; i += 4) {
            int s0 = d_eid[i], s1 = d_eid[i+1], s2 = d_eid[i+2], s3 = d_eid[i+3];
            float4 v0 = *(const float4*)&d_g[s0 * H + lane * 4];
            float4 v1 = *(const float4*)&d_g[s1 * H + lane * 4];
            float4 v2 = *(const float4*)&d_g[s2 * H + lane * 4];
            float4 v3 = *(const float4*)&d_g[s3 * H + lane * 4];
            a0.x += v0.x; a0.y += v0.y; a0.z += v0.z; a0.w += v0.w;
            a1.x += v1.x; a1.y += v1.y; a1.z += v1.z; a1.w += v1.w;
            a2.x += v2.x; a2.y += v2.y; a2.z += v2.z; a2.w += v2.w;
            a3.x += v3.x; a3.y += v3.y; a3.z += v3.z; a3.w += v3.w;
        }
        for (; i < end; i++) {
            int s0 = d_eid[i];
            float4 v0 = *(const float4*)&d_g[s0 * H + lane * 4];
            a0.x += v0.x; a0.y += v0.y; a0.z += v0.z; a0.w += v0.w;
        }
        float4 r;
        r.x = (a0.x + a1.x) + (a2.x + a3.x);
        r.y = (a0.y + a1.y) + (a2.y + a3.y);
        r.z = (a0.z + a1.z) + (a2.z + a3.z);
        r.w = (a0.w + a1.w) + (a2.w + a3.w);
        *(float4*)&d_agg[dst * H + lane * 4] = r;
    }
}

// ---------------- final FC ----------------
__global__ void __launch_bounds__(NT) fc_kernel(const float* __restrict__ P,
                                                const float* __restrict__ Wfc,
                                                const float* __restrict__ bfc,
                                                float* __restrict__ out)
{
    __shared__ float sW[H * OUT];
    __shared__ float sbf[OUT];
    int t = threadIdx.x;
    for (int i = t; i < H * OUT; i += NT) sW[i] = Wfc[i];
    if (t < OUT) sbf[t] = bfc[t];
    __syncthreads();
    int idx = blockIdx.x * NT + t;
    int r = idx >> 2, q = idx & 3;
    if (r >= N_PATIENT) return;
    float s0 = sbf[2 * q], s1 = sbf[2 * q + 1];
    #pragma unroll 8
    for (int c4 = 0; c4 < H / 4; c4++) {
        float4 a = *(const float4*)&P[r * H + c4 * 4];
        s0 += a.x * sW[(c4*4    ) * OUT + 2*q];  s1 += a.x * sW[(c4*4    ) * OUT + 2*q + 1];
        s0 += a.y * sW[(c4*4 + 1) * OUT + 2*q];  s1 += a.y * sW[(c4*4 + 1) * OUT + 2*q + 1];
        s0 += a.z * sW[(c4*4 + 2) * OUT + 2*q];  s1 += a.z * sW[(c4*4 + 2) * OUT + 2*q + 1];
        s0 += a.w * sW[(c4*4 + 3) * OUT + 2*q];  s1 += a.w * sW[(c4*4 + 3) * OUT + 2*q + 1];
    }
    out[r * OUT + 2 * q]     = s0;
    out[r * OUT + 2 * q + 1] = s1;
}

// ---------------- launch ----------------
extern "C" void kernel_launch(void* const* d_in, const int* in_sizes, int n_in,
                              void* d_out, int out_size)
{
    const float* x_p  = (const float*)d_in[0];
    const float* x_g  = (const float*)d_in[1];
    const int*   eidx = (const int*)  d_in[2];
    const float* W_p1 = (const float*)d_in[3];
    const float* b_p1 = (const float*)d_in[4];
    const float* W_p2 = (const float*)d_in[5];
    const float* b_p2 = (const float*)d_in[6];
    const float* W_g1 = (const float*)d_in[7];
    const float* b_g1 = (const float*)d_in[8];
    const float* W_g2 = (const float*)d_in[9];
    const float* b_g2 = (const float*)d_in[10];
    const float* W1_l = (const float*)d_in[11];
    const float* b1_l = (const float*)d_in[12];
    const float* W1_r = (const float*)d_in[13];
    const float* W2_l = (const float*)d_in[14];
    const float* b2_l = (const float*)d_in[15];
    const float* W2_r = (const float*)d_in[16];
    const float* W_fc = (const float*)d_in[17];
    const float* b_fc = (const float*)d_in[18];
    float* out = (float*)d_out;

    float* g_g   = nullptr; cudaGetSymbolAddress((void**)&g_g,   d_g);
    float* g_agg = nullptr; cudaGetSymbolAddress((void**)&g_agg, d_agg);
    float* g_p   = nullptr; cudaGetSymbolAddress((void**)&g_p,   d_p);
    float* g_t   = nullptr; cudaGetSymbolAddress((void**)&g_t,   d_t);
    __nv_bfloat16* g_w = nullptr; cudaGetSymbolAddress((void**)&g_w, d_wsp);
    auto wsp = [&](int m) { return g_w + (size_t)m * H * 256; };

    auto kGM = mlp_fused<G_DIM>;
    auto kPM = mlp_fused<P_DIM>;

    const int smGM = 2*(MTILE*2*G_DIM*2) + 2*(MTILE*256*2) + 1024;  // 32K + 128K + 1K
    const int smPM = 2*(MTILE*2*P_DIM*2) + 2*(MTILE*256*2) + 1024;  // 64K + 128K + 1K
    const int smS  = MTILE*256*2 + 2*(H*256*2) + 1024;              // 193 KB

    cudaFuncSetAttribute(kGM, cudaFuncAttributeMaxDynamicSharedMemorySize, smGM);
    cudaFuncSetAttribute(kPM, cudaFuncAttributeMaxDynamicSharedMemorySize, smPM);
    cudaFuncSetAttribute(mma_sage, cudaFuncAttributeMaxDynamicSharedMemorySize, smS);

    PrepArgs pa;
    pa.src[0] = W_g1; pa.K[0] = 32;
    pa.src[1] = W_g2; pa.K[1] = 128;
    pa.src[2] = W_p1; pa.K[2] = 64;
    pa.src[3] = W_p2; pa.K[3] = 128;
    pa.src[4] = W1_l; pa.K[4] = 128;
    pa.src[5] = W1_r; pa.K[5] = 128;
    pa.src[6] = W2_l; pa.K[6] = 128;
    pa.src[7] = W2_r; pa.K[7] = 128;

    const int edge_blocks = (N_EDGE + NT - 1) / NT;
    const int cnt_blocks  = (N_PATIENT + NT - 1) / NT;
    const int fc_blocks   = (N_PATIENT * 4 + NT - 1) / NT;

    prep_kernel<<<dim3((H * 256 + NT - 1) / NT, 8), NT>>>(pa);

    // CSR build (independent of MLPs)
    zero_cnt_kernel<<<cnt_blocks, NT>>>();
    hist_kernel<<<edge_blocks, NT>>>(eidx);
    scan_kernel<<<1, 1024>>>();
    fill_kernel<<<edge_blocks, NT>>>(eidx);

    // fused node MLPs
    kGM<<<148, NTT, smGM>>>(x_g, wsp(0), b_g1, wsp(1), b_g2, g_g, N_GENE);
    kPM<<<148, NTT, smPM>>>(x_p, wsp(2), b_p1, wsp(3), b_p2, g_p, N_PATIENT);

    // aggregation: gather-sum (no atomics), also initializes all agg rows
    gather_kernel<<<296, NT>>>();

    // SAGE layers
    mma_sage<<<148, NTT, smS>>>(g_agg, g_p, wsp(4), wsp(5), b1_l, g_t, N_PATIENT);
    mma_sage<<<148, NTT, smS>>>(g_agg, g_t, wsp(6), wsp(7), b2_l, g_p, N_PATIENT);

    // final FC
    fc_kernel<<<fc_blocks, NT>>>(g_p, W_fc, b_fc, out);
}

// round 17
// speedup vs baseline: 2.6881x; 1.2446x over previous
#include <cuda_runtime.h>
#include <cuda_bf16.h>
#include <cstdint>

#define N_PATIENT 50000
#define N_GENE    20000
#define N_EDGE    640000
#define P_DIM 64
#define G_DIM 32
#define H     128
#define OUT   8
#define NT    256
#define NTT   512
#define MTILE 128
#define SCAN_BLOCKS ((N_PATIENT + NT - 1) / NT)   // 196

#if defined(__CUDA_ARCH__) && (defined(__CUDA_ARCH_FEAT_SM103_ALL) || \
    defined(__CUDA_ARCH_FEAT_SM100_ALL) || defined(__CUDA_ARCH_FEAT_SM101_ALL))
#define HAS_TC5 1
#else
#define HAS_TC5 0
#endif

// ---------------- device scratch ----------------
__device__ float d_g  [N_GENE    * H];
__device__ float d_agg[N_PATIENT * H];
__device__ float d_p  [N_PATIENT * H];
__device__ float d_t  [N_PATIENT * H];
__device__ __nv_bfloat16 d_wsp[8][H * 256];   // dedup split weights [H][2K]
__device__ int d_cnt[N_PATIENT];
__device__ int d_off[N_PATIENT + 1];
__device__ int d_pos[N_PATIENT];
__device__ int d_eid[N_EDGE];
__device__ int d_bsum[SCAN_BLOCKS];

// ---------------- ptx helpers ----------------
__device__ __forceinline__ uint32_t cvta_s(const void* p) {
    uint32_t a;
    asm("{.reg .u64 t; cvta.to.shared.u64 t, %1; cvt.u32.u64 %0, t;}" : "=r"(a) : "l"(p));
    return a;
}
__device__ __forceinline__ bool elect1() {
    uint32_t p;
    asm volatile("{.reg .pred p; elect.sync _|p, 0xFFFFFFFF; selp.b32 %0,1,0,p;}" : "=r"(p));
    return p != 0;
}
__device__ __forceinline__ void sts128(uint32_t addr, uint32_t a, uint32_t b,
                                       uint32_t c, uint32_t d) {
    asm volatile("st.shared.v4.b32 [%0], {%1,%2,%3,%4};"
                 :: "r"(addr), "r"(a), "r"(b), "r"(c), "r"(d) : "memory");
}
__device__ __forceinline__ void sts32(uint32_t addr, uint32_t v) {
    asm volatile("st.shared.b32 [%0], %1;" :: "r"(addr), "r"(v) : "memory");
}
__device__ __forceinline__ void mbar_init(uint32_t addr, uint32_t cnt) {
    asm volatile("mbarrier.init.shared.b64 [%0], %1;" :: "r"(addr), "r"(cnt) : "memory");
}
__device__ __forceinline__ void mbar_inval(uint32_t addr) {
    asm volatile("mbarrier.inval.shared.b64 [%0];" :: "r"(addr) : "memory");
}
__device__ __forceinline__ void mbar_wait(uint32_t mbar, uint32_t parity) {
    uint32_t done;
    asm volatile(
        "{\n\t.reg .pred p;\n\t"
        "mbarrier.try_wait.parity.acquire.cta.shared::cta.b64 p, [%1], %2;\n\t"
        "selp.b32 %0, 1, 0, p;\n\t}"
        : "=r"(done) : "r"(mbar), "r"(parity) : "memory");
    if (!done) {
        asm volatile(
            "{\n\t.reg .pred P1;\n\t"
            "WAIT_LOOP_%=:\n\t"
            "mbarrier.try_wait.parity.acquire.cta.shared::cta.b64 P1, [%0], %1, 0x989680;\n\t"
            "@P1 bra.uni WAIT_DONE_%=;\n\t"
            "bra.uni WAIT_LOOP_%=;\n\t"
            "WAIT_DONE_%=:\n\t}"
            :: "r"(mbar), "r"(parity) : "memory");
    }
}
__device__ __forceinline__ void tmem_alloc(uint32_t dst_smem, uint32_t ncols) {
#if HAS_TC5
    asm volatile("tcgen05.alloc.cta_group::1.sync.aligned.shared::cta.b32 [%0], %1;"
                 :: "r"(dst_smem), "r"(ncols) : "memory");
#endif
}
__device__ __forceinline__ void tmem_dealloc(uint32_t tmem, uint32_t ncols) {
#if HAS_TC5
    asm volatile("tcgen05.dealloc.cta_group::1.sync.aligned.b32 %0, %1;" :: "r"(tmem), "r"(ncols));
#endif
}
__device__ __forceinline__ void mma_f16_ss(uint32_t d_tmem, uint64_t a_desc,
                                           uint64_t b_desc, uint32_t idesc, bool en) {
#if HAS_TC5
    uint32_t e = en ? 1u : 0u;
    asm volatile(
        "{\n\t.reg .pred p;\n\t"
        "setp.ne.u32 p, %5, 0;\n\t"
        "tcgen05.mma.cta_group::1.kind::f16 [%0], %1, %2, %3, {%4,%4,%4,%4}, p;\n\t}"
        :: "r"(d_tmem), "l"(a_desc), "l"(b_desc), "r"(idesc), "r"(0u), "r"(e)
        : "memory");
#endif
}
__device__ __forceinline__ void mma_commit(uint32_t mbar) {
#if HAS_TC5
    asm volatile("tcgen05.commit.cta_group::1.mbarrier::arrive::one.shared::cluster.b64 [%0];"
                 :: "r"(mbar) : "memory");
#else
    asm volatile("mbarrier.arrive.shared.b64 _, [%0];" :: "r"(mbar) : "memory");
#endif
}
__device__ __forceinline__ void fence_async_proxy() {
    asm volatile("fence.proxy.async.shared::cta;" ::: "memory");
}
__device__ __forceinline__ void tc_fence_after() {
#if HAS_TC5
    asm volatile("tcgen05.fence::after_thread_sync;" ::: "memory");
#endif
}
__device__ __forceinline__ void tc_fence_before() {
#if HAS_TC5
    asm volatile("tcgen05.fence::before_thread_sync;" ::: "memory");
#endif
}
__device__ __forceinline__ void tc_wait_ld() {
#if HAS_TC5
    asm volatile("tcgen05.wait::ld.sync.aligned;" ::: "memory");
#endif
}
__device__ __forceinline__ void ldtm32(uint32_t* r, uint32_t tmem_addr) {
#if HAS_TC5
    asm volatile(
        "tcgen05.ld.sync.aligned.32x32b.x32.b32 "
        "{%0, %1, %2, %3, %4, %5, %6, %7, "
        " %8, %9, %10, %11, %12, %13, %14, %15, "
        " %16, %17, %18, %19, %20, %21, %22, %23, "
        " %24, %25, %26, %27, %28, %29, %30, %31}, [%32];"
        : "=r"(r[0]),  "=r"(r[1]),  "=r"(r[2]),  "=r"(r[3]),
          "=r"(r[4]),  "=r"(r[5]),  "=r"(r[6]),  "=r"(r[7]),
          "=r"(r[8]),  "=r"(r[9]),  "=r"(r[10]), "=r"(r[11]),
          "=r"(r[12]), "=r"(r[13]), "=r"(r[14]), "=r"(r[15]),
          "=r"(r[16]), "=r"(r[17]), "=r"(r[18]), "=r"(r[19]),
          "=r"(r[20]), "=r"(r[21]), "=r"(r[22]), "=r"(r[23]),
          "=r"(r[24]), "=r"(r[25]), "=r"(r[26]), "=r"(r[27]),
          "=r"(r[28]), "=r"(r[29]), "=r"(r[30]), "=r"(r[31])
        : "r"(tmem_addr));
#else
    for (int i = 0; i < 32; i++) r[i] = 0u;
#endif
}

static constexpr uint64_t DESC_BASE =
    (2ull << 61) | (1ull << 46) | (64ull << 32) | (1ull << 16);
__device__ __forceinline__ uint64_t make_desc(uint32_t addr) {
    return DESC_BASE | ((uint64_t)(addr >> 4) & 0x3FFF);
}
__device__ __forceinline__ uint32_t swz(uint32_t off) { return off ^ ((off >> 3) & 0x70); }
__device__ __forceinline__ uint32_t coff(int c) { return (c >> 2) * 1024 + (c & 3) * 2; }

// ---------------- weight split prep: W[K][H] f32 -> W'[H][2K] bf16 ([W0,W1]) ----
struct PrepArgs { const float* src[8]; int K[8]; };
__global__ void __launch_bounds__(NT) prep_kernel(PrepArgs a) {
    int m = blockIdx.y;
    int K = a.K[m], KP = 2 * K;
    const float* W = a.src[m];
    __nv_bfloat16* D = d_wsp[m];
    int i = blockIdx.x * blockDim.x + threadIdx.x;
    if (i >= H * KP) return;
    int c = i / KP, s = i % KP;
    __nv_bfloat16 v;
    if (s < K) {
        v = __float2bfloat16(W[s * H + c]);
    } else {
        float w = W[(s - K) * H + c];
        float w0 = __bfloat162float(__float2bfloat16(w));
        v = __float2bfloat16(w - w0);
    }
    D[c * KP + s] = v;
}

// ---------------- staging ----------------
__device__ __forceinline__ uint32_t offA(int row, int s) {
    return ((row >> 3) + (s >> 6) * 16) * 1024 + (row & 7) * 128 + (s & 63) * 2;
}
template<int K>
__device__ __forceinline__ void stageA(uint32_t sA, const float* __restrict__ A,
                                       int row0, int nrows, int t) {
    const int GP = K / 8;
    for (int g = t; g < MTILE * GP; g += NTT) {
        int row = g / GP, k8 = g % GP;
        int gr = row0 + row;
        float4 v0 = make_float4(0.f,0.f,0.f,0.f), v1 = v0;
        if (gr < nrows) {
            const float4* src = (const float4*)&A[gr * K + k8 * 8];
            v0 = src[0]; v1 = src[1];
        }
        float f[8] = {v0.x, v0.y, v0.z, v0.w, v1.x, v1.y, v1.z, v1.w};
        uint32_t p0[4], p1[4];
        #pragma unroll
        for (int j = 0; j < 4; j++) {
            __nv_bfloat16 b0 = __float2bfloat16(f[2*j]);
            __nv_bfloat16 b1 = __float2bfloat16(f[2*j+1]);
            __nv_bfloat162 q0 = __halves2bfloat162(b0, b1);
            p0[j] = *(uint32_t*)&q0;
            __nv_bfloat16 c0 = __float2bfloat16(f[2*j]   - __bfloat162float(b0));
            __nv_bfloat16 c1 = __float2bfloat16(f[2*j+1] - __bfloat162float(b1));
            __nv_bfloat162 q1 = __halves2bfloat162(c0, c1);
            p1[j] = *(uint32_t*)&q1;
        }
        int s = k8 * 8;
        sts128(sA + swz(offA(row, s)),     p0[0], p0[1], p0[2], p0[3]);
        sts128(sA + swz(offA(row, K + s)), p1[0], p1[1], p1[2], p1[3]);
    }
}
template<int K>
__device__ __forceinline__ void stageB(uint32_t sB, const __nv_bfloat16* __restrict__ Wp, int t) {
    const int KP = 2 * K, GP = KP / 8;
    const uint4* src = (const uint4*)Wp;
    for (int g = t; g < H * GP; g += NTT) {
        int r = g / GP, s8 = g % GP;
        uint4 v = src[g];
        sts128(sB + swz(offA(r, s8 * 8)), v.x, v.y, v.z, v.w);
    }
}

// 3-phase dedup MMA chain: D += A0*W0 + A0*W1 + A1*W0
template<int K>
__device__ __forceinline__ void issue_phases(uint32_t Dtm, uint64_t dA, uint64_t dB,
                                             uint32_t idesc, bool first) {
    const int K16 = K / 16;
    #pragma unroll 1
    for (int c = 0; c < K16; c++)
        mma_f16_ss(Dtm, dA + coff(c),       dB + coff(c),       idesc, !(first && c == 0));
    #pragma unroll 1
    for (int c = 0; c < K16; c++)
        mma_f16_ss(Dtm, dA + coff(c),       dB + coff(c + K16), idesc, true);
    #pragma unroll 1
    for (int c = 0; c < K16; c++)
        mma_f16_ss(Dtm, dA + coff(c + K16), dB + coff(c),       idesc, true);
}

// epilogue: 8 warps, full 128x128 f32 tile from TMEM + bias (+relu) -> Y (global)
template<bool RELU>
__device__ __forceinline__ void epilogue(uint32_t Dtm, const float* sb,
                                         float* __restrict__ Y, int row0, int nrows,
                                         int wid, int lane) {
    if (wid >= 8) return;
    tc_fence_after();
    const int r = (wid & 3) * 32 + lane;
    const int gr = row0 + r;
    #pragma unroll 1
    for (int i = 0; i < 2; i++) {
        int cb = (wid >> 2) + i * 2;
        uint32_t rg[32];
        ldtm32(rg, Dtm + cb * 32);
        tc_wait_ld();
        tc_fence_before();
        if (gr < nrows) {
            const int cbase = cb * 32;
            #pragma unroll
            for (int j = 0; j < 32; j += 4) {
                float4 o;
                o.x = __uint_as_float(rg[j])     + sb[cbase + j];
                o.y = __uint_as_float(rg[j + 1]) + sb[cbase + j + 1];
                o.z = __uint_as_float(rg[j + 2]) + sb[cbase + j + 2];
                o.w = __uint_as_float(rg[j + 3]) + sb[cbase + j + 3];
                if (RELU) {
                    o.x = fmaxf(o.x, 0.f); o.y = fmaxf(o.y, 0.f);
                    o.z = fmaxf(o.z, 0.f); o.w = fmaxf(o.w, 0.f);
                }
                *(float4*)&Y[gr * H + cbase + j] = o;
            }
        }
    }
}

// mid epilogue: TMEM -> bias+relu -> bf16 split -> SMEM A-tile (256 slots/row)
__device__ __forceinline__ void epilogue_to_smem(uint32_t Dtm, const float* sb,
                                                 uint32_t sA2, int wid, int lane) {
    if (wid >= 8) return;
    tc_fence_after();
    const int r = (wid & 3) * 32 + lane;
    #pragma unroll 1
    for (int i = 0; i < 2; i++) {
        int cb = (wid >> 2) + i * 2;
        uint32_t rg[32];
        ldtm32(rg, Dtm + cb * 32);
        tc_wait_ld();
        tc_fence_before();
        const int cbase = cb * 32;
        #pragma unroll
        for (int j = 0; j < 32; j += 2) {
            float v0 = fmaxf(__uint_as_float(rg[j])     + sb[cbase + j], 0.f);
            float v1 = fmaxf(__uint_as_float(rg[j + 1]) + sb[cbase + j + 1], 0.f);
            __nv_bfloat16 b0 = __float2bfloat16(v0);
            __nv_bfloat16 b1 = __float2bfloat16(v1);
            __nv_bfloat162 q0 = __halves2bfloat162(b0, b1);
            __nv_bfloat16 c0 = __float2bfloat16(v0 - __bfloat162float(b0));
            __nv_bfloat16 c1 = __float2bfloat16(v1 - __bfloat162float(b1));
            __nv_bfloat162 q1 = __halves2bfloat162(c0, c1);
            sts32(sA2 + swz(offA(r, cbase + j)),       *(uint32_t*)&q0);
            sts32(sA2 + swz(offA(r, 128 + cbase + j)), *(uint32_t*)&q1);
        }
    }
}

static constexpr uint32_t IDESC_BF16 =
    (1u << 4) | (1u << 7) | (1u << 10) | (16u << 17) | (8u << 24);

// ---------------- fused 2-layer MLP (tcgen05) ----------------
template<int K1>
__global__ void __launch_bounds__(NTT, 1) __cluster_dims__(1, 1, 1)
mlp_fused(const float* __restrict__ X,
          const __nv_bfloat16* __restrict__ W1p, const float* __restrict__ b1,
          const __nv_bfloat16* __restrict__ W2p, const float* __restrict__ b2,
          float* __restrict__ Y, int nrows)
{
    extern __shared__ char smx[];
    __shared__ uint32_t s_tmemptr;
    __shared__ __align__(8) unsigned long long s_mbar;
    __shared__ float sb1[H], sb2[H];

    const int t = threadIdx.x, lane = t & 31, wid = t >> 5;
    const uint32_t mbar = cvta_s(&s_mbar);
    const uint32_t SZ1 = MTILE * 2 * K1 * 2;
    uint32_t sA1 = (cvta_s(smx) + 1023u) & ~1023u;
    uint32_t sB1 = sA1 + SZ1;
    uint32_t sA2 = sB1 + SZ1;
    uint32_t sB2 = sA2 + MTILE * 256 * 2;

    if (wid == 0) tmem_alloc(cvta_s(&s_tmemptr), 256);
    if (t == 0) mbar_init(mbar, 1);
    if (t < H) { sb1[t] = b1[t]; sb2[t] = b2[t]; }
    stageB<K1>(sB1, W1p, t);
    stageB<H>(sB2, W2p, t);
    __syncthreads();
    const uint32_t tmem = s_tmemptr;
    const uint64_t dA1 = make_desc(sA1), dB1 = make_desc(sB1);
    const uint64_t dA2 = make_desc(sA2), dB2 = make_desc(sB2);

    const int ntiles = (nrows + MTILE - 1) / MTILE;
    uint32_t ph = 0;

    #pragma unroll 1
    for (int tile = blockIdx.x; tile < ntiles; tile += gridDim.x) {
        const int row0 = tile * MTILE;
        stageA<K1>(sA1, X, row0, nrows, t);
        __syncthreads();
        if (wid == 0 && elect1()) {
            fence_async_proxy();
            issue_phases<K1>(tmem, dA1, dB1, IDESC_BF16, true);
            mma_commit(mbar);
        }
        mbar_wait(mbar, ph); ph ^= 1;
        epilogue_to_smem(tmem, sb1, sA2, wid, lane);
        __syncthreads();
        if (wid == 0 && elect1()) {
            fence_async_proxy();
            issue_phases<H>(tmem + 128, dA2, dB2, IDESC_BF16, true);
            mma_commit(mbar);
        }
        mbar_wait(mbar, ph); ph ^= 1;
        epilogue<false>(tmem + 128, sb2, Y, row0, nrows, wid, lane);
        __syncthreads();
    }

    __syncthreads();
    if (t == 0) mbar_inval(mbar);
    __syncthreads();
    if (wid == 0) tmem_dealloc(tmem, 256);
}

// ---------------- dual-operand SAGE pass ----------------
__global__ void __launch_bounds__(NTT, 1) __cluster_dims__(1, 1, 1)
mma_sage(const float* __restrict__ A1, const float* __restrict__ A2,
         const __nv_bfloat16* __restrict__ W1p, const __nv_bfloat16* __restrict__ W2p,
         const float* __restrict__ bias, float* __restrict__ Y, int nrows)
{
    extern __shared__ char smx[];
    __shared__ uint32_t s_tmemptr;
    __shared__ __align__(8) unsigned long long s_mbar;
    __shared__ float sb[H];

    const int t = threadIdx.x, lane = t & 31, wid = t >> 5;
    const uint32_t mbar = cvta_s(&s_mbar);
    const uint32_t A_BYTES = MTILE * 256 * 2;
    uint32_t sA  = (cvta_s(smx) + 1023u) & ~1023u;
    uint32_t sB1 = sA + A_BYTES;
    uint32_t sB2 = sB1 + H * 256 * 2;

    if (wid == 0) tmem_alloc(cvta_s(&s_tmemptr), 256);
    if (t == 0) mbar_init(mbar, 1);
    if (t < H) sb[t] = bias[t];
    stageB<H>(sB1, W1p, t);
    stageB<H>(sB2, W2p, t);
    __syncthreads();
    const uint32_t tmem = s_tmemptr;
    const uint64_t dA  = make_desc(sA);
    const uint64_t dB1 = make_desc(sB1);
    const uint64_t dB2 = make_desc(sB2);

    const int ntiles = (nrows + MTILE - 1) / MTILE;
    uint32_t ph = 0;
    int prevRow0 = 0, pbuf = 0;
    bool havePrev = false;

    #pragma unroll 1
    for (int tl = blockIdx.x; tl < ntiles; tl += gridDim.x) {
        const int cbuf = havePrev ? (pbuf ^ 1) : 0;
        if (havePrev) { mbar_wait(mbar, ph); ph ^= 1; __syncthreads(); }
        stageA<H>(sA, A1, tl * MTILE, nrows, t);
        __syncthreads();
        if (wid == 0 && elect1()) {
            fence_async_proxy();
            issue_phases<H>(tmem + cbuf * 128, dA, dB1, IDESC_BF16, true);
            mma_commit(mbar);
        }
        if (havePrev)
            epilogue<true>(tmem + pbuf * 128, sb, Y, prevRow0, nrows, wid, lane);
        mbar_wait(mbar, ph); ph ^= 1;
        __syncthreads();
        stageA<H>(sA, A2, tl * MTILE, nrows, t);
        __syncthreads();
        if (wid == 0 && elect1()) {
            fence_async_proxy();
            issue_phases<H>(tmem + cbuf * 128, dA, dB2, IDESC_BF16, false);
            mma_commit(mbar);
        }
        prevRow0 = tl * MTILE; pbuf = cbuf; havePrev = true;
    }
    if (havePrev) {
        mbar_wait(mbar, ph); ph ^= 1;
        epilogue<true>(tmem + pbuf * 128, sb, Y, prevRow0, nrows, wid, lane);
    }

    __syncthreads();
    if (t == 0) mbar_inval(mbar);
    __syncthreads();
    if (wid == 0) tmem_dealloc(tmem, 256);
}

// ---------------- CSR build + gather aggregation ----------------
__global__ void __launch_bounds__(NT) zero_cnt_kernel() {
    int i = blockIdx.x * blockDim.x + threadIdx.x;
    if (i < N_PATIENT) d_cnt[i] = 0;
}
__global__ void __launch_bounds__(NT) hist_kernel(const int* __restrict__ edges) {
    int e = blockIdx.x * blockDim.x + threadIdx.x;
    if (e < N_EDGE) atomicAdd(&d_cnt[edges[N_EDGE + e]], 1);
}
// phase 1: per-block exclusive scan of 256-chunk; block total -> d_bsum
__global__ void __launch_bounds__(NT) scan1_kernel() {
    __shared__ int wsum[8];
    const int t = threadIdx.x, lane = t & 31, wid = t >> 5;
    int i = blockIdx.x * NT + t;
    int v = (i < N_PATIENT) ? d_cnt[i] : 0;
    int x = v;
    #pragma unroll
    for (int d = 1; d < 32; d <<= 1) {
        int y = __shfl_up_sync(0xFFFFFFFF, x, d);
        if (lane >= d) x += y;
    }
    if (lane == 31) wsum[wid] = x;
    __syncthreads();
    if (t < 8) {
        int s = wsum[t];
        #pragma unroll
        for (int d = 1; d < 8; d <<= 1) {
            int y = __shfl_up_sync(0xFF, s, d);
            if (t >= d) s += y;
        }
        wsum[t] = s;
    }
    __syncthreads();
    int wbase = (wid == 0) ? 0 : wsum[wid - 1];
    int excl = wbase + (x - v);
    if (i < N_PATIENT) d_off[i] = excl;          // block-local exclusive
    if (t == NT - 1) d_bsum[blockIdx.x] = wbase + x;   // block total
}
// phase 2: single block scans the 196 block sums (exclusive, in place)
__global__ void __launch_bounds__(NT) scan2_kernel() {
    __shared__ int wsum[8];
    const int t = threadIdx.x, lane = t & 31, wid = t >> 5;
    int v = (t < SCAN_BLOCKS) ? d_bsum[t] : 0;
    int x = v;
    #pragma unroll
    for (int d = 1; d < 32; d <<= 1) {
        int y = __shfl_up_sync(0xFFFFFFFF, x, d);
        if (lane >= d) x += y;
    }
    if (lane == 31) wsum[wid] = x;
    __syncthreads();
    if (t < 8) {
        int s = wsum[t];
        #pragma unroll
        for (int d = 1; d < 8; d <<= 1) {
            int y = __shfl_up_sync(0xFF, s, d);
            if (t >= d) s += y;
        }
        wsum[t] = s;
    }
    __syncthreads();
    int wbase = (wid == 0) ? 0 : wsum[wid - 1];
    if (t < SCAN_BLOCKS) d_bsum[t] = wbase + (x - v);
    if (t == 0) d_off[N_PATIENT] = wsum[7];      // grand total = N_EDGE
}
// phase 3: add block base; init d_pos
__global__ void __launch_bounds__(NT) scan3_kernel() {
    int i = blockIdx.x * NT + threadIdx.x;
    if (i < N_PATIENT) {
        int o = d_off[i] + d_bsum[blockIdx.x];
        d_off[i] = o;
        d_pos[i] = o;
    }
}
__global__ void __launch_bounds__(NT) fill_kernel(const int* __restrict__ edges) {
    int e = blockIdx.x * blockDim.x + threadIdx.x;
    if (e >= N_EDGE) return;
    int dst = edges[N_EDGE + e];
    int slot = atomicAdd(&d_pos[dst], 1);
    d_eid[slot] = edges[e];
}
// one warp per dst row: agg[dst] = sum over neighbors g[src] (no atomics)
__global__ void __launch_bounds__(NT) gather_kernel() {
    const int lane = threadIdx.x & 31;
    const int w = (blockIdx.x * blockDim.x + threadIdx.x) >> 5;
    const int nw = (gridDim.x * blockDim.x) >> 5;
    for (int dst = w; dst < N_PATIENT; dst += nw) {
        int beg = d_off[dst], end = d_off[dst + 1];
        float4 a0 = make_float4(0.f,0.f,0.f,0.f), a1 = a0, a2 = a0, a3 = a0;
        int i = beg;
        for (; i + 4 <= end; i += 4) {
            int s0 = d_eid[i], s1 = d_eid[i+1], s2 = d_eid[i+2], s3 = d_eid[i+3];
            float4 v0 = *(const float4*)&d_g[s0 * H + lane * 4];
            float4 v1 = *(const float4*)&d_g[s1 * H + lane * 4];
            float4 v2 = *(const float4*)&d_g[s2 * H + lane * 4];
            float4 v3 = *(const float4*)&d_g[s3 * H + lane * 4];
            a0.x += v0.x; a0.y += v0.y; a0.z += v0.z; a0.w += v0.w;
            a1.x += v1.x; a1.y += v1.y; a1.z += v1.z; a1.w += v1.w;
            a2.x += v2.x; a2.y += v2.y; a2.z += v2.z; a2.w += v2.w;
            a3.x += v3.x; a3.y += v3.y; a3.z += v3.z; a3.w += v3.w;
        }
        for (; i < end; i++) {
            int s0 = d_eid[i];
            float4 v0 = *(const float4*)&d_g[s0 * H + lane * 4];
            a0.x += v0.x; a0.y += v0.y; a0.z += v0.z; a0.w += v0.w;
        }
        float4 r;
        r.x = (a0.x + a1.x) + (a2.x + a3.x);
        r.y = (a0.y + a1.y) + (a2.y + a3.y);
        r.z = (a0.z + a1.z) + (a2.z + a3.z);
        r.w = (a0.w + a1.w) + (a2.w + a3.w);
        *(float4*)&d_agg[dst * H + lane * 4] = r;
    }
}

// ---------------- final FC ----------------
__global__ void __launch_bounds__(NT) fc_kernel(const float* __restrict__ P,
                                                const float* __restrict__ Wfc,
                                                const float* __restrict__ bfc,
                                                float* __restrict__ out)
{
    __shared__ float sW[H * OUT];
    __shared__ float sbf[OUT];
    int t = threadIdx.x;
    for (int i = t; i < H * OUT; i += NT) sW[i] = Wfc[i];
    if (t < OUT) sbf[t] = bfc[t];
    __syncthreads();
    int idx = blockIdx.x * NT + t;
    int r = idx >> 2, q = idx & 3;
    if (r >= N_PATIENT) return;
    float s0 = sbf[2 * q], s1 = sbf[2 * q + 1];
    #pragma unroll 8
    for (int c4 = 0; c4 < H / 4; c4++) {
        float4 a = *(const float4*)&P[r * H + c4 * 4];
        s0 += a.x * sW[(c4*4    ) * OUT + 2*q];  s1 += a.x * sW[(c4*4    ) * OUT + 2*q + 1];
        s0 += a.y * sW[(c4*4 + 1) * OUT + 2*q];  s1 += a.y * sW[(c4*4 + 1) * OUT + 2*q + 1];
        s0 += a.z * sW[(c4*4 + 2) * OUT + 2*q];  s1 += a.z * sW[(c4*4 + 2) * OUT + 2*q + 1];
        s0 += a.w * sW[(c4*4 + 3) * OUT + 2*q];  s1 += a.w * sW[(c4*4 + 3) * OUT + 2*q + 1];
    }
    out[r * OUT + 2 * q]     = s0;
    out[r * OUT + 2 * q + 1] = s1;
}

// ---------------- launch ----------------
extern "C" void kernel_launch(void* const* d_in, const int* in_sizes, int n_in,
                              void* d_out, int out_size)
{
    const float* x_p  = (const float*)d_in[0];
    const float* x_g  = (const float*)d_in[1];
    const int*   eidx = (const int*)  d_in[2];
    const float* W_p1 = (const float*)d_in[3];
    const float* b_p1 = (const float*)d_in[4];
    const float* W_p2 = (const float*)d_in[5];
    const float* b_p2 = (const float*)d_in[6];
    const float* W_g1 = (const float*)d_in[7];
    const float* b_g1 = (const float*)d_in[8];
    const float* W_g2 = (const float*)d_in[9];
    const float* b_g2 = (const float*)d_in[10];
    const float* W1_l = (const float*)d_in[11];
    const float* b1_l = (const float*)d_in[12];
    const float* W1_r = (const float*)d_in[13];
    const float* W2_l = (const float*)d_in[14];
    const float* b2_l = (const float*)d_in[15];
    const float* W2_r = (const float*)d_in[16];
    const float* W_fc = (const float*)d_in[17];
    const float* b_fc = (const float*)d_in[18];
    float* out = (float*)d_out;

    float* g_g   = nullptr; cudaGetSymbolAddress((void**)&g_g,   d_g);
    float* g_agg = nullptr; cudaGetSymbolAddress((void**)&g_agg, d_agg);
    float* g_p   = nullptr; cudaGetSymbolAddress((void**)&g_p,   d_p);
    float* g_t   = nullptr; cudaGetSymbolAddress((void**)&g_t,   d_t);
    __nv_bfloat16* g_w = nullptr; cudaGetSymbolAddress((void**)&g_w, d_wsp);
    auto wsp = [&](int m) { return g_w + (size_t)m * H * 256; };

    auto kGM = mlp_fused<G_DIM>;
    auto kPM = mlp_fused<P_DIM>;

    const int smGM = 2*(MTILE*2*G_DIM*2) + 2*(MTILE*256*2) + 1024;
    const int smPM = 2*(MTILE*2*P_DIM*2) + 2*(MTILE*256*2) + 1024;
    const int smS  = MTILE*256*2 + 2*(H*256*2) + 1024;

    cudaFuncSetAttribute(kGM, cudaFuncAttributeMaxDynamicSharedMemorySize, smGM);
    cudaFuncSetAttribute(kPM, cudaFuncAttributeMaxDynamicSharedMemorySize, smPM);
    cudaFuncSetAttribute(mma_sage, cudaFuncAttributeMaxDynamicSharedMemorySize, smS);

    PrepArgs pa;
    pa.src[0] = W_g1; pa.K[0] = 32;
    pa.src[1] = W_g2; pa.K[1] = 128;
    pa.src[2] = W_p1; pa.K[2] = 64;
    pa.src[3] = W_p2; pa.K[3] = 128;
    pa.src[4] = W1_l; pa.K[4] = 128;
    pa.src[5] = W1_r; pa.K[5] = 128;
    pa.src[6] = W2_l; pa.K[6] = 128;
    pa.src[7] = W2_r; pa.K[7] = 128;

    const int edge_blocks = (N_EDGE + NT - 1) / NT;
    const int fc_blocks   = (N_PATIENT * 4 + NT - 1) / NT;

    prep_kernel<<<dim3((H * 256 + NT - 1) / NT, 8), NT>>>(pa);

    // CSR build (parallel 3-phase scan)
    zero_cnt_kernel<<<SCAN_BLOCKS, NT>>>();
    hist_kernel<<<edge_blocks, NT>>>(eidx);
    scan1_kernel<<<SCAN_BLOCKS, NT>>>();
    scan2_kernel<<<1, NT>>>();
    scan3_kernel<<<SCAN_BLOCKS, NT>>>();
    fill_kernel<<<edge_blocks, NT>>>(eidx);

    // fused node MLPs
    kGM<<<148, NTT, smGM>>>(x_g, wsp(0), b_g1, wsp(1), b_g2, g_g, N_GENE);
    kPM<<<148, NTT, smPM>>>(x_p, wsp(2), b_p1, wsp(3), b_p2, g_p, N_PATIENT);

    // aggregation: gather-sum (no atomics)
    gather_kernel<<<592, NT>>>();

    // SAGE layers
    mma_sage<<<148, NTT, smS>>>(g_agg, g_p, wsp(4), wsp(5), b1_l, g_t, N_PATIENT);
    mma_sage<<<148, NTT, smS>>>(g_agg, g_t, wsp(6), wsp(7), b2_l, g_p, N_PATIENT);

    // final FC
    fc_kernel<<<fc_blocks, NT>>>(g_p, W_fc, b_fc, out);
}